// round 1
// baseline (speedup 1.0000x reference)
#include <cuda_runtime.h>
#include <cuda_bf16.h>
#include <math.h>

// Problem constants
#define BATCH 4
#define SEQ   2048
#define EMBD  1024
#define NHEAD 16
#define HDIM  64
#define MTOT  (BATCH*SEQ)          // 8192
#define SCALE 0.03125f             // C^-0.5 = 1/32

// Scratch buffers: q,k,v,attn each [B,H,T,D] fp32
__device__ float g_q[BATCH*NHEAD*SEQ*HDIM];
__device__ float g_k[BATCH*NHEAD*SEQ*HDIM];
__device__ float g_v[BATCH*NHEAD*SEQ*HDIM];
__device__ float g_attn[BATCH*NHEAD*SEQ*HDIM];

// ---------------------------------------------------------------------------
// Kernel A: QKV projection.
// out[b,h,t,d] = sum_c x[b,t,c] * W[h,c,d]
// grid = (MTOT/64, NHEAD, 3), block = 256 (16x16), 64x64 tile, BK=32
// ---------------------------------------------------------------------------
__global__ __launch_bounds__(256) void qkv_kernel(
    const float* __restrict__ x,
    const float* __restrict__ Wq,
    const float* __restrict__ Wk,
    const float* __restrict__ Wv)
{
    __shared__ float Xs[64*36];   // stride 36 (pad, float4-aligned)
    __shared__ float Ws[32*64];   // stride 64

    const int bt0 = blockIdx.x * 64;
    const int h   = blockIdx.y;
    const int z   = blockIdx.z;
    const float* W = (z == 0) ? Wq : (z == 1) ? Wk : Wv;
    float* outp    = (z == 0) ? g_q : (z == 1) ? g_k : g_v;
    const float* Wh = W + (size_t)h * EMBD * HDIM;

    const int tid = threadIdx.x;
    const int tx = tid & 15;
    const int ty = tid >> 4;

    float acc[4][4];
#pragma unroll
    for (int i = 0; i < 4; i++)
#pragma unroll
        for (int j = 0; j < 4; j++) acc[i][j] = 0.f;

    for (int c0 = 0; c0 < EMBD; c0 += 32) {
        // load X tile: 64 rows x 32 cols = 512 float4
#pragma unroll
        for (int it = 0; it < 2; it++) {
            int idx = tid + it * 256;          // 0..511
            int r = idx >> 3, c4 = idx & 7;
            float4 v = *(const float4*)&x[(size_t)(bt0 + r) * EMBD + c0 + c4 * 4];
            *(float4*)&Xs[r * 36 + c4 * 4] = v;
        }
        // load W tile: 32 rows x 64 cols = 512 float4
#pragma unroll
        for (int it = 0; it < 2; it++) {
            int idx = tid + it * 256;
            int cc = idx >> 4, d4 = idx & 15;
            float4 v = *(const float4*)&Wh[(size_t)(c0 + cc) * HDIM + d4 * 4];
            *(float4*)&Ws[cc * 64 + d4 * 4] = v;
        }
        __syncthreads();
#pragma unroll
        for (int cc = 0; cc < 32; cc++) {
            float4 bv = *(const float4*)&Ws[cc * 64 + tx * 4];
            float a0 = Xs[(ty * 4 + 0) * 36 + cc];
            float a1 = Xs[(ty * 4 + 1) * 36 + cc];
            float a2 = Xs[(ty * 4 + 2) * 36 + cc];
            float a3 = Xs[(ty * 4 + 3) * 36 + cc];
            acc[0][0] += a0 * bv.x; acc[0][1] += a0 * bv.y; acc[0][2] += a0 * bv.z; acc[0][3] += a0 * bv.w;
            acc[1][0] += a1 * bv.x; acc[1][1] += a1 * bv.y; acc[1][2] += a1 * bv.z; acc[1][3] += a1 * bv.w;
            acc[2][0] += a2 * bv.x; acc[2][1] += a2 * bv.y; acc[2][2] += a2 * bv.z; acc[2][3] += a2 * bv.w;
            acc[3][0] += a3 * bv.x; acc[3][1] += a3 * bv.y; acc[3][2] += a3 * bv.z; acc[3][3] += a3 * bv.w;
        }
        __syncthreads();
    }

#pragma unroll
    for (int i = 0; i < 4; i++) {
        int bt = bt0 + ty * 4 + i;
        int b = bt >> 11, t = bt & 2047;
        float* orow = outp + ((size_t)(b * NHEAD + h) * SEQ + t) * HDIM;
#pragma unroll
        for (int j = 0; j < 4; j++)
            orow[tx * 4 + j] = acc[i][j];
    }
}

// ---------------------------------------------------------------------------
// Kernel B: causal flash attention per (b,h). 64x64 tiles, online softmax.
// grid = (SEQ/64=32, B*H=64), block = 256 (16x16). Dynamic smem 4*64*65*4.
// ---------------------------------------------------------------------------
__global__ __launch_bounds__(256) void attn_kernel()
{
    extern __shared__ float sm[];
    float* Qs = sm;               // 64*65
    float* Ks = Qs + 64 * 65;
    float* Vs = Ks + 64 * 65;
    float* Ps = Vs + 64 * 65;

    const int qt = blockIdx.x;
    const int bh = blockIdx.y;
    const int m0 = qt * 64;
    const int tid = threadIdx.x;
    const int tx = tid & 15;
    const int ty = tid >> 4;

    const float* qptr = g_q + (size_t)bh * SEQ * HDIM;
    const float* kptr = g_k + (size_t)bh * SEQ * HDIM;
    const float* vptr = g_v + (size_t)bh * SEQ * HDIM;

    // load Q tile (pre-scaled)
    for (int idx = tid; idx < 64 * 64; idx += 256) {
        int r = idx >> 6, d = idx & 63;
        Qs[r * 65 + d] = qptr[(size_t)(m0 + r) * HDIM + d] * SCALE;
    }

    float m_i[4], l_i[4], o[4][4];
#pragma unroll
    for (int i = 0; i < 4; i++) {
        m_i[i] = -INFINITY; l_i[i] = 0.f;
#pragma unroll
        for (int j = 0; j < 4; j++) o[i][j] = 0.f;
    }

    for (int jt = 0; jt <= qt; jt++) {
        const int n0 = jt * 64;
        __syncthreads();   // previous PV done (also covers initial Q load)
        for (int idx = tid; idx < 64 * 64; idx += 256) {
            int r = idx >> 6, d = idx & 63;
            Ks[r * 65 + d] = kptr[(size_t)(n0 + r) * HDIM + d];
            Vs[r * 65 + d] = vptr[(size_t)(n0 + r) * HDIM + d];
        }
        __syncthreads();

        // S = Q K^T (64x64)
        float s[4][4];
#pragma unroll
        for (int i = 0; i < 4; i++)
#pragma unroll
            for (int j = 0; j < 4; j++) s[i][j] = 0.f;
#pragma unroll 8
        for (int d = 0; d < 64; d++) {
            float a0 = Qs[(ty * 4 + 0) * 65 + d];
            float a1 = Qs[(ty * 4 + 1) * 65 + d];
            float a2 = Qs[(ty * 4 + 2) * 65 + d];
            float a3 = Qs[(ty * 4 + 3) * 65 + d];
            float b0 = Ks[(tx * 4 + 0) * 65 + d];
            float b1 = Ks[(tx * 4 + 1) * 65 + d];
            float b2 = Ks[(tx * 4 + 2) * 65 + d];
            float b3 = Ks[(tx * 4 + 3) * 65 + d];
            s[0][0] += a0 * b0; s[0][1] += a0 * b1; s[0][2] += a0 * b2; s[0][3] += a0 * b3;
            s[1][0] += a1 * b0; s[1][1] += a1 * b1; s[1][2] += a1 * b2; s[1][3] += a1 * b3;
            s[2][0] += a2 * b0; s[2][1] += a2 * b1; s[2][2] += a2 * b2; s[2][3] += a2 * b3;
            s[3][0] += a3 * b0; s[3][1] += a3 * b1; s[3][2] += a3 * b2; s[3][3] += a3 * b3;
        }

        // causal mask (diagonal tile only)
        if (jt == qt) {
#pragma unroll
            for (int i = 0; i < 4; i++)
#pragma unroll
                for (int j = 0; j < 4; j++)
                    if (tx * 4 + j > ty * 4 + i) s[i][j] = -INFINITY;
        }

        // online softmax per row group (16 tx lanes share a row)
#pragma unroll
        for (int i = 0; i < 4; i++) {
            float mx = fmaxf(fmaxf(s[i][0], s[i][1]), fmaxf(s[i][2], s[i][3]));
#pragma unroll
            for (int off = 1; off < 16; off <<= 1)
                mx = fmaxf(mx, __shfl_xor_sync(0xffffffffu, mx, off));
            float mnew = fmaxf(m_i[i], mx);
            float alpha = __expf(m_i[i] - mnew);
            float p0 = __expf(s[i][0] - mnew);
            float p1 = __expf(s[i][1] - mnew);
            float p2 = __expf(s[i][2] - mnew);
            float p3 = __expf(s[i][3] - mnew);
            float rs = p0 + p1 + p2 + p3;
#pragma unroll
            for (int off = 1; off < 16; off <<= 1)
                rs += __shfl_xor_sync(0xffffffffu, rs, off);
            l_i[i] = l_i[i] * alpha + rs;
            m_i[i] = mnew;
#pragma unroll
            for (int j = 0; j < 4; j++) o[i][j] *= alpha;
            float* pr = &Ps[(ty * 4 + i) * 65 + tx * 4];
            pr[0] = p0; pr[1] = p1; pr[2] = p2; pr[3] = p3;
        }
        __syncthreads();

        // O += P @ V
#pragma unroll 8
        for (int n = 0; n < 64; n++) {
            float a0 = Ps[(ty * 4 + 0) * 65 + n];
            float a1 = Ps[(ty * 4 + 1) * 65 + n];
            float a2 = Ps[(ty * 4 + 2) * 65 + n];
            float a3 = Ps[(ty * 4 + 3) * 65 + n];
            float b0 = Vs[n * 65 + tx * 4 + 0];
            float b1 = Vs[n * 65 + tx * 4 + 1];
            float b2 = Vs[n * 65 + tx * 4 + 2];
            float b3 = Vs[n * 65 + tx * 4 + 3];
            o[0][0] += a0 * b0; o[0][1] += a0 * b1; o[0][2] += a0 * b2; o[0][3] += a0 * b3;
            o[1][0] += a1 * b0; o[1][1] += a1 * b1; o[1][2] += a1 * b2; o[1][3] += a1 * b3;
            o[2][0] += a2 * b0; o[2][1] += a2 * b1; o[2][2] += a2 * b2; o[2][3] += a2 * b3;
            o[3][0] += a3 * b0; o[3][1] += a3 * b1; o[3][2] += a3 * b2; o[3][3] += a3 * b3;
        }
    }

    // write normalized O to g_attn [B,H,T,D]
#pragma unroll
    for (int i = 0; i < 4; i++) {
        float inv_l = 1.f / l_i[i];
        float* orow = g_attn + ((size_t)bh * SEQ + m0 + ty * 4 + i) * HDIM;
#pragma unroll
        for (int j = 0; j < 4; j++)
            orow[tx * 4 + j] = o[i][j] * inv_l;
    }
}

// ---------------------------------------------------------------------------
// Kernel C: output projection. out[bt,n] = sum_j attn[bt,j]*Wproj[n,j] + b[n]
// attn logical [bt, j] with j = h*64+d, stored as [B,H,T,D].
// grid = (MTOT/64, EMBD/64), block 256.
// ---------------------------------------------------------------------------
__global__ __launch_bounds__(256) void proj_kernel(
    const float* __restrict__ Wproj,
    const float* __restrict__ bproj,
    float* __restrict__ out)
{
    __shared__ float As[64*36];
    __shared__ float Wn[64*33];

    const int bt0 = blockIdx.x * 64;
    const int n0  = blockIdx.y * 64;
    const int tid = threadIdx.x;
    const int tx = tid & 15;
    const int ty = tid >> 4;

    float acc[4][4];
#pragma unroll
    for (int i = 0; i < 4; i++)
#pragma unroll
        for (int j = 0; j < 4; j++) acc[i][j] = 0.f;

    for (int j0 = 0; j0 < EMBD; j0 += 32) {
        const int h = j0 >> 6;
        const int doff = j0 & 63;
        // A tile: 64 rows x 32 cols
#pragma unroll
        for (int it = 0; it < 2; it++) {
            int idx = tid + it * 256;
            int r = idx >> 3, c4 = idx & 7;
            int bt = bt0 + r;
            int b = bt >> 11, t = bt & 2047;
            float4 v = *(const float4*)&g_attn[((size_t)(b * NHEAD + h) * SEQ + t) * HDIM + doff + c4 * 4];
            *(float4*)&As[r * 36 + c4 * 4] = v;
        }
        // W tile: 64 n-rows x 32 cc-cols (row-major in smem, stride 33)
#pragma unroll
        for (int it = 0; it < 2; it++) {
            int idx = tid + it * 256;
            int n = idx >> 3, c4 = idx & 7;
            float4 v = *(const float4*)&Wproj[(size_t)(n0 + n) * EMBD + j0 + c4 * 4];
            float* wp = &Wn[n * 33 + c4 * 4];
            wp[0] = v.x; wp[1] = v.y; wp[2] = v.z; wp[3] = v.w;
        }
        __syncthreads();
#pragma unroll
        for (int cc = 0; cc < 32; cc++) {
            float a0 = As[(ty * 4 + 0) * 36 + cc];
            float a1 = As[(ty * 4 + 1) * 36 + cc];
            float a2 = As[(ty * 4 + 2) * 36 + cc];
            float a3 = As[(ty * 4 + 3) * 36 + cc];
            float b0 = Wn[(tx * 4 + 0) * 33 + cc];
            float b1 = Wn[(tx * 4 + 1) * 33 + cc];
            float b2 = Wn[(tx * 4 + 2) * 33 + cc];
            float b3 = Wn[(tx * 4 + 3) * 33 + cc];
            acc[0][0] += a0 * b0; acc[0][1] += a0 * b1; acc[0][2] += a0 * b2; acc[0][3] += a0 * b3;
            acc[1][0] += a1 * b0; acc[1][1] += a1 * b1; acc[1][2] += a1 * b2; acc[1][3] += a1 * b3;
            acc[2][0] += a2 * b0; acc[2][1] += a2 * b1; acc[2][2] += a2 * b2; acc[2][3] += a2 * b3;
            acc[3][0] += a3 * b0; acc[3][1] += a3 * b1; acc[3][2] += a3 * b2; acc[3][3] += a3 * b3;
        }
        __syncthreads();
    }

#pragma unroll
    for (int i = 0; i < 4; i++) {
        int bt = bt0 + ty * 4 + i;
        float* orow = out + (size_t)bt * EMBD;
#pragma unroll
        for (int j = 0; j < 4; j++) {
            int c = n0 + tx * 4 + j;
            orow[c] = acc[i][j] + bproj[c];
        }
    }
}

// ---------------------------------------------------------------------------
extern "C" void kernel_launch(void* const* d_in, const int* in_sizes, int n_in,
                              void* d_out, int out_size)
{
    const float* x     = (const float*)d_in[0];
    const float* Wq    = (const float*)d_in[1];
    const float* Wk    = (const float*)d_in[2];
    const float* Wv    = (const float*)d_in[3];
    const float* Wproj = (const float*)d_in[4];
    const float* bproj = (const float*)d_in[5];
    float* out = (float*)d_out;

    // QKV projections
    qkv_kernel<<<dim3(MTOT / 64, NHEAD, 3), 256>>>(x, Wq, Wk, Wv);

    // attention (needs > 48KB dynamic smem)
    const int attn_smem = 4 * 64 * 65 * sizeof(float);
    cudaFuncSetAttribute(attn_kernel, cudaFuncAttributeMaxDynamicSharedMemorySize, attn_smem);
    attn_kernel<<<dim3(SEQ / 64, BATCH * NHEAD), 256, attn_smem>>>();

    // output projection
    proj_kernel<<<dim3(MTOT / 64, EMBD / 64), 256>>>(Wproj, bproj, out);
}

// round 2
// speedup vs baseline: 2.7754x; 2.7754x over previous
#include <cuda_runtime.h>
#include <math.h>
#include <stdint.h>

#define BATCH 4
#define SEQ   2048
#define EMBD  1024
#define NHEAD 16
#define HDIM  64
#define MTOT  (BATCH*SEQ)
// softmax done in log2 domain: fold log2(e) into the QK scale (C^-0.5 = 1/32)
#define QK_SCALE_L2 (0.03125f * 1.44269504088896340736f)

// scratch: q,k,v,attn each [B,H,T,D] fp32
__device__ float g_q[BATCH*NHEAD*SEQ*HDIM];
__device__ float g_k[BATCH*NHEAD*SEQ*HDIM];
__device__ float g_v[BATCH*NHEAD*SEQ*HDIM];
__device__ float g_attn[BATCH*NHEAD*SEQ*HDIM];

// ---------------------------------------------------------------------------
__device__ __forceinline__ uint32_t f2tf(float f) {
    uint32_t u; asm("cvt.rna.tf32.f32 %0, %1;" : "=r"(u) : "f"(f)); return u;
}
__device__ __forceinline__ uint32_t smem_u32(const void* p) {
    return (uint32_t)__cvta_generic_to_shared(p);
}
// ldmatrix x4 of 16B rows; for tf32 each 8x8 b16 matrix is an 8x4 tf32 quadrant.
__device__ __forceinline__ void ldsm4(uint32_t* r, uint32_t a) {
    asm volatile("ldmatrix.sync.aligned.m8n8.x4.shared.b16 {%0,%1,%2,%3}, [%4];"
        : "=r"(r[0]), "=r"(r[1]), "=r"(r[2]), "=r"(r[3]) : "r"(a) : "memory");
}
__device__ __forceinline__ void mma8(float* c, const uint32_t* a, uint32_t b0, uint32_t b1) {
    asm volatile("mma.sync.aligned.m16n8k8.row.col.f32.tf32.tf32.f32 "
        "{%0,%1,%2,%3},{%4,%5,%6,%7},{%8,%9},{%0,%1,%2,%3};"
        : "+f"(c[0]), "+f"(c[1]), "+f"(c[2]), "+f"(c[3])
        : "r"(a[0]), "r"(a[1]), "r"(a[2]), "r"(a[3]), "r"(b0), "r"(b1));
}

// ---------------------------------------------------------------------------
// Kernel A: fused QKV projection, TF32 tensor cores.
// Block tile: 128 (bt) x 192 (q64|k64|v64) for one head. grid (64, 16), 256 thr.
// Warp layout: 4 m-warps x 2 n-warps; warp tile 32 x 96.
// ---------------------------------------------------------------------------
__global__ __launch_bounds__(256) void qkv_kernel(
    const float* __restrict__ x,
    const float* __restrict__ Wq,
    const float* __restrict__ Wk,
    const float* __restrict__ Wv)
{
    __shared__ uint32_t As[128*36];   // [m][k] pad 36
    __shared__ uint32_t Bs[192*36];   // [n][k] pad 36 (n = z*64+d)

    const int bt0 = blockIdx.x * 128;
    const int h   = blockIdx.y;
    const int tid = threadIdx.x;
    const int lane = tid & 31, wid = tid >> 5;
    const int wm = wid & 3, wn = wid >> 2;
    const int lr = lane & 7, ls = lane >> 3;

    const float* Wz[3] = { Wq + (size_t)h * EMBD * HDIM,
                           Wk + (size_t)h * EMBD * HDIM,
                           Wv + (size_t)h * EMBD * HDIM };

    float acc[2][12][4];
#pragma unroll
    for (int mt = 0; mt < 2; mt++)
#pragma unroll
        for (int nt = 0; nt < 12; nt++)
#pragma unroll
            for (int c = 0; c < 4; c++) acc[mt][nt][c] = 0.f;

    const int a_row = wm * 32 + lr + ((ls & 1) << 3);
    const int a_kof = (ls >> 1) << 2;
    const int b_row = wn * 96 + lr + ((ls >> 1) << 3);
    const int b_kof = (ls & 1) << 2;

    for (int c0 = 0; c0 < EMBD; c0 += 32) {
        __syncthreads();
        // As: 128x32 floats = 1024 float4
#pragma unroll
        for (int it = 0; it < 4; it++) {
            int idx = tid + it * 256;
            int r = idx >> 3, c4 = (idx & 7) * 4;
            float4 v = *(const float4*)&x[(size_t)(bt0 + r) * EMBD + c0 + c4];
            uint32_t* d = &As[r * 36 + c4];
            d[0] = f2tf(v.x); d[1] = f2tf(v.y); d[2] = f2tf(v.z); d[3] = f2tf(v.w);
        }
        // Bs: per z, transpose 32(c) x 64(d) -> [d][c]
#pragma unroll
        for (int z = 0; z < 3; z++) {
            const float* W = Wz[z];
#pragma unroll
            for (int it = 0; it < 2; it++) {
                int idx = tid + it * 256;
                int cc = idx >> 4, d4 = (idx & 15) * 4;
                float4 v = *(const float4*)&W[(size_t)(c0 + cc) * HDIM + d4];
                uint32_t* dst = &Bs[(z * 64 + d4) * 36 + cc];
                dst[0]   = f2tf(v.x);
                dst[36]  = f2tf(v.y);
                dst[72]  = f2tf(v.z);
                dst[108] = f2tf(v.w);
            }
        }
        __syncthreads();
#pragma unroll
        for (int kk = 0; kk < 32; kk += 8) {
            uint32_t a[2][4];
#pragma unroll
            for (int mt = 0; mt < 2; mt++)
                ldsm4(a[mt], smem_u32(&As[(a_row + mt * 16) * 36 + kk + a_kof]));
#pragma unroll
            for (int g = 0; g < 6; g++) {
                uint32_t b[4];
                ldsm4(b, smem_u32(&Bs[(b_row + g * 16) * 36 + kk + b_kof]));
                mma8(acc[0][2*g+0], a[0], b[0], b[1]);
                mma8(acc[0][2*g+1], a[0], b[2], b[3]);
                mma8(acc[1][2*g+0], a[1], b[0], b[1]);
                mma8(acc[1][2*g+1], a[1], b[2], b[3]);
            }
        }
    }

    // epilogue: scatter to g_q/g_k/g_v [B,H,T,D]
#pragma unroll
    for (int mt = 0; mt < 2; mt++) {
        int row = bt0 + wm * 32 + mt * 16 + (lane >> 2);
        int b = row >> 11, t = row & 2047;
#pragma unroll
        for (int nt = 0; nt < 12; nt++) {
            int nbase = wn * 96 + nt * 8;
            int z = nbase >> 6;
            int d = (nbase & 63) + 2 * (lane & 3);
            float* base = (z == 0 ? g_q : z == 1 ? g_k : g_v)
                        + (((size_t)(b * NHEAD + h)) * SEQ + t) * HDIM;
            *(float2*)&base[d] = make_float2(acc[mt][nt][0], acc[mt][nt][1]);
            *(float2*)&base[8 * HDIM + d] = make_float2(acc[mt][nt][2], acc[mt][nt][3]);
        }
    }
}

// ---------------------------------------------------------------------------
// Kernel B: causal flash attention, TF32 tensor cores.
// Q tile 128 rows, K/V tiles 64. grid (16, 64), 256 thr (8 warps, m16 each).
// ---------------------------------------------------------------------------
__global__ __launch_bounds__(256) void attn_kernel()
{
    extern __shared__ uint32_t sm[];
    uint32_t* Qs = sm;                 // [128][68] tf32, pre-scaled by 1/32*log2e
    uint32_t* Ks = Qs + 128 * 68;      // [64 kr][68 d]
    uint32_t* Vt = Ks + 64 * 68;       // [64 d][68 kr]  (V transposed)
    uint32_t* Ps = Vt + 64 * 68;       // [128][68]

    const int qt = blockIdx.x, bh = blockIdx.y;
    const int m0 = qt * 128;
    const int tid = threadIdx.x;
    const int lane = tid & 31, wid = tid >> 5;
    const int lr = lane & 7, ls = lane >> 3;

    const float* qp = g_q + (size_t)bh * SEQ * HDIM;
    const float* kp = g_k + (size_t)bh * SEQ * HDIM;
    const float* vp = g_v + (size_t)bh * SEQ * HDIM;

    // Q load: 128x64 = 2048 float4
#pragma unroll
    for (int it = 0; it < 8; it++) {
        int idx = tid + it * 256;
        int r = idx >> 4, d4 = (idx & 15) * 4;
        float4 v = *(const float4*)&qp[(size_t)(m0 + r) * HDIM + d4];
        uint32_t* d = &Qs[r * 68 + d4];
        d[0] = f2tf(v.x * QK_SCALE_L2); d[1] = f2tf(v.y * QK_SCALE_L2);
        d[2] = f2tf(v.z * QK_SCALE_L2); d[3] = f2tf(v.w * QK_SCALE_L2);
    }

    float o[8][4];
#pragma unroll
    for (int nt = 0; nt < 8; nt++)
#pragma unroll
        for (int c = 0; c < 4; c++) o[nt][c] = 0.f;
    float mrow[2] = { -INFINITY, -INFINITY };
    float lrow[2] = { 0.f, 0.f };

    const int s_arow = wid * 16 + lr + ((ls & 1) << 3);   // A rows (Q / P)
    const int s_akof = (ls >> 1) << 2;
    const int s_brow = lr + ((ls >> 1) << 3);             // B rows (K / Vt)
    const int s_bkof = (ls & 1) << 2;

    const int jtmax = 2 * qt + 1;
    for (int jt = 0; jt <= jtmax; jt++) {
        const int n0 = jt * 64;
        __syncthreads();
        // K tile 64x64
#pragma unroll
        for (int it = 0; it < 4; it++) {
            int idx = tid + it * 256;
            int r = idx >> 4, d4 = (idx & 15) * 4;
            float4 v = *(const float4*)&kp[(size_t)(n0 + r) * HDIM + d4];
            uint32_t* d = &Ks[r * 68 + d4];
            d[0] = f2tf(v.x); d[1] = f2tf(v.y); d[2] = f2tf(v.z); d[3] = f2tf(v.w);
        }
        // V tile transposed -> Vt[d][kr]
#pragma unroll
        for (int it = 0; it < 4; it++) {
            int idx = tid + it * 256;
            int r = idx >> 4, d4 = (idx & 15) * 4;
            float4 v = *(const float4*)&vp[(size_t)(n0 + r) * HDIM + d4];
            Vt[(d4 + 0) * 68 + r] = f2tf(v.x);
            Vt[(d4 + 1) * 68 + r] = f2tf(v.y);
            Vt[(d4 + 2) * 68 + r] = f2tf(v.z);
            Vt[(d4 + 3) * 68 + r] = f2tf(v.w);
        }
        __syncthreads();

        // S = Q K^T  (m16 x 64, k = 64)
        float s[8][4];
#pragma unroll
        for (int nt = 0; nt < 8; nt++)
#pragma unroll
            for (int c = 0; c < 4; c++) s[nt][c] = 0.f;
#pragma unroll
        for (int kk = 0; kk < 64; kk += 8) {
            uint32_t a[4];
            ldsm4(a, smem_u32(&Qs[s_arow * 68 + kk + s_akof]));
#pragma unroll
            for (int g = 0; g < 4; g++) {
                uint32_t b[4];
                ldsm4(b, smem_u32(&Ks[(g * 16 + s_brow) * 68 + kk + s_bkof]));
                mma8(s[2*g+0], a, b[0], b[1]);
                mma8(s[2*g+1], a, b[2], b[3]);
            }
        }

        // causal mask (only the last two kv tiles of this q block need it)
        const int grow = m0 + wid * 16 + (lane >> 2);
        if (jt >= 2 * qt) {
#pragma unroll
            for (int nt = 0; nt < 8; nt++) {
                int col = n0 + nt * 8 + 2 * (lane & 3);
                if (col     > grow)     s[nt][0] = -INFINITY;
                if (col + 1 > grow)     s[nt][1] = -INFINITY;
                if (col     > grow + 8) s[nt][2] = -INFINITY;
                if (col + 1 > grow + 8) s[nt][3] = -INFINITY;
            }
        }

        // online softmax (log2 domain), rows grow and grow+8
        float mx0 = -INFINITY, mx1 = -INFINITY;
#pragma unroll
        for (int nt = 0; nt < 8; nt++) {
            mx0 = fmaxf(mx0, fmaxf(s[nt][0], s[nt][1]));
            mx1 = fmaxf(mx1, fmaxf(s[nt][2], s[nt][3]));
        }
        mx0 = fmaxf(mx0, __shfl_xor_sync(0xffffffffu, mx0, 1));
        mx0 = fmaxf(mx0, __shfl_xor_sync(0xffffffffu, mx0, 2));
        mx1 = fmaxf(mx1, __shfl_xor_sync(0xffffffffu, mx1, 1));
        mx1 = fmaxf(mx1, __shfl_xor_sync(0xffffffffu, mx1, 2));
        float mn0 = fmaxf(mrow[0], mx0), mn1 = fmaxf(mrow[1], mx1);
        float al0 = exp2f(mrow[0] - mn0), al1 = exp2f(mrow[1] - mn1);
        float rs0 = 0.f, rs1 = 0.f;
#pragma unroll
        for (int nt = 0; nt < 8; nt++) {
            s[nt][0] = exp2f(s[nt][0] - mn0); rs0 += s[nt][0];
            s[nt][1] = exp2f(s[nt][1] - mn0); rs0 += s[nt][1];
            s[nt][2] = exp2f(s[nt][2] - mn1); rs1 += s[nt][2];
            s[nt][3] = exp2f(s[nt][3] - mn1); rs1 += s[nt][3];
        }
        rs0 += __shfl_xor_sync(0xffffffffu, rs0, 1);
        rs0 += __shfl_xor_sync(0xffffffffu, rs0, 2);
        rs1 += __shfl_xor_sync(0xffffffffu, rs1, 1);
        rs1 += __shfl_xor_sync(0xffffffffu, rs1, 2);
        lrow[0] = lrow[0] * al0 + rs0; mrow[0] = mn0;
        lrow[1] = lrow[1] * al1 + rs1; mrow[1] = mn1;
#pragma unroll
        for (int nt = 0; nt < 8; nt++) {
            o[nt][0] *= al0; o[nt][1] *= al0;
            o[nt][2] *= al1; o[nt][3] *= al1;
        }

        // write P (tf32) to this warp's private strip of Ps
        {
            int pr = wid * 16 + (lane >> 2);
#pragma unroll
            for (int nt = 0; nt < 8; nt++) {
                int col = nt * 8 + 2 * (lane & 3);
                *(uint2*)&Ps[pr * 68 + col]       = make_uint2(f2tf(s[nt][0]), f2tf(s[nt][1]));
                *(uint2*)&Ps[(pr + 8) * 68 + col] = make_uint2(f2tf(s[nt][2]), f2tf(s[nt][3]));
            }
        }
        __syncwarp();

        // O += P @ V  (k = kr 64, n = d 64)
#pragma unroll
        for (int kk = 0; kk < 64; kk += 8) {
            uint32_t a[4];
            ldsm4(a, smem_u32(&Ps[s_arow * 68 + kk + s_akof]));
#pragma unroll
            for (int g = 0; g < 4; g++) {
                uint32_t b[4];
                ldsm4(b, smem_u32(&Vt[(g * 16 + s_brow) * 68 + kk + s_bkof]));
                mma8(o[2*g+0], a, b[0], b[1]);
                mma8(o[2*g+1], a, b[2], b[3]);
            }
        }
    }

    // epilogue: normalize and store to g_attn
    {
        float inv0 = 1.f / lrow[0], inv1 = 1.f / lrow[1];
        int row = m0 + wid * 16 + (lane >> 2);
        float* op = g_attn + ((size_t)bh * SEQ + row) * HDIM;
#pragma unroll
        for (int nt = 0; nt < 8; nt++) {
            int col = nt * 8 + 2 * (lane & 3);
            *(float2*)&op[col] = make_float2(o[nt][0] * inv0, o[nt][1] * inv0);
            *(float2*)&op[8 * HDIM + col] = make_float2(o[nt][2] * inv1, o[nt][3] * inv1);
        }
    }
}

// ---------------------------------------------------------------------------
// Kernel C: output projection, TF32. Tile 128x128, grid (64, 8), 256 thr.
// out[bt,n] = sum_j attn[bt,j] * Wproj[n,j] + bias[n]
// ---------------------------------------------------------------------------
__global__ __launch_bounds__(256) void proj_kernel(
    const float* __restrict__ Wproj,
    const float* __restrict__ bproj,
    float* __restrict__ out)
{
    __shared__ uint32_t As[128*36];   // [m][k]
    __shared__ uint32_t Bs[128*36];   // [n][k] (Wproj rows are already n-major)

    const int bt0 = blockIdx.x * 128;
    const int n0  = blockIdx.y * 128;
    const int tid = threadIdx.x;
    const int lane = tid & 31, wid = tid >> 5;
    const int wm = wid & 3, wn = wid >> 2;
    const int lr = lane & 7, ls = lane >> 3;

    float acc[2][8][4];
#pragma unroll
    for (int mt = 0; mt < 2; mt++)
#pragma unroll
        for (int nt = 0; nt < 8; nt++)
#pragma unroll
            for (int c = 0; c < 4; c++) acc[mt][nt][c] = 0.f;

    const int a_row = wm * 32 + lr + ((ls & 1) << 3);
    const int a_kof = (ls >> 1) << 2;
    const int b_row = wn * 64 + lr + ((ls >> 1) << 3);
    const int b_kof = (ls & 1) << 2;

    for (int j0 = 0; j0 < EMBD; j0 += 32) {
        __syncthreads();
        const int h = j0 >> 6, dof = j0 & 63;
#pragma unroll
        for (int it = 0; it < 4; it++) {
            int idx = tid + it * 256;
            int r = idx >> 3, c4 = (idx & 7) * 4;
            int bt = bt0 + r, b = bt >> 11, t = bt & 2047;
            float4 v = *(const float4*)&g_attn[(((size_t)(b * NHEAD + h)) * SEQ + t) * HDIM + dof + c4];
            uint32_t* d = &As[r * 36 + c4];
            d[0] = f2tf(v.x); d[1] = f2tf(v.y); d[2] = f2tf(v.z); d[3] = f2tf(v.w);
        }
#pragma unroll
        for (int it = 0; it < 4; it++) {
            int idx = tid + it * 256;
            int n = idx >> 3, c4 = (idx & 7) * 4;
            float4 v = *(const float4*)&Wproj[(size_t)(n0 + n) * EMBD + j0 + c4];
            uint32_t* d = &Bs[n * 36 + c4];
            d[0] = f2tf(v.x); d[1] = f2tf(v.y); d[2] = f2tf(v.z); d[3] = f2tf(v.w);
        }
        __syncthreads();
#pragma unroll
        for (int kk = 0; kk < 32; kk += 8) {
            uint32_t a[2][4];
#pragma unroll
            for (int mt = 0; mt < 2; mt++)
                ldsm4(a[mt], smem_u32(&As[(a_row + mt * 16) * 36 + kk + a_kof]));
#pragma unroll
            for (int g = 0; g < 4; g++) {
                uint32_t b[4];
                ldsm4(b, smem_u32(&Bs[(b_row + g * 16) * 36 + kk + b_kof]));
                mma8(acc[0][2*g+0], a[0], b[0], b[1]);
                mma8(acc[0][2*g+1], a[0], b[2], b[3]);
                mma8(acc[1][2*g+0], a[1], b[0], b[1]);
                mma8(acc[1][2*g+1], a[1], b[2], b[3]);
            }
        }
    }

#pragma unroll
    for (int mt = 0; mt < 2; mt++) {
        int row = bt0 + wm * 32 + mt * 16 + (lane >> 2);
        float* o0 = out + (size_t)row * EMBD;
        float* o1 = out + (size_t)(row + 8) * EMBD;
#pragma unroll
        for (int nt = 0; nt < 8; nt++) {
            int col = n0 + wn * 64 + nt * 8 + 2 * (lane & 3);
            float b0 = bproj[col], b1 = bproj[col + 1];
            *(float2*)&o0[col] = make_float2(acc[mt][nt][0] + b0, acc[mt][nt][1] + b1);
            *(float2*)&o1[col] = make_float2(acc[mt][nt][2] + b0, acc[mt][nt][3] + b1);
        }
    }
}

// ---------------------------------------------------------------------------
extern "C" void kernel_launch(void* const* d_in, const int* in_sizes, int n_in,
                              void* d_out, int out_size)
{
    const float* x     = (const float*)d_in[0];
    const float* Wq    = (const float*)d_in[1];
    const float* Wk    = (const float*)d_in[2];
    const float* Wv    = (const float*)d_in[3];
    const float* Wproj = (const float*)d_in[4];
    const float* bproj = (const float*)d_in[5];
    float* out = (float*)d_out;

    qkv_kernel<<<dim3(MTOT / 128, NHEAD), 256>>>(x, Wq, Wk, Wv);

    const int attn_smem = (128*68 + 64*68 + 64*68 + 128*68) * (int)sizeof(uint32_t);
    cudaFuncSetAttribute(attn_kernel, cudaFuncAttributeMaxDynamicSharedMemorySize, attn_smem);
    attn_kernel<<<dim3(SEQ / 128, BATCH * NHEAD), 256, attn_smem>>>();

    proj_kernel<<<dim3(MTOT / 128, EMBD / 128), 256>>>(Wproj, bproj, out);
}

// round 3
// speedup vs baseline: 3.7572x; 1.3538x over previous
#include <cuda_runtime.h>
#include <math.h>
#include <stdint.h>

#define BATCH 4
#define SEQ   2048
#define EMBD  1024
#define NHEAD 16
#define HDIM  64
#define MTOT  (BATCH*SEQ)            // 8192
#define NQKV  (3*NHEAD*HDIM)         // 3072
#define QK_SCALE_L2 (0.03125f * 1.44269504088896340736f)

// tf32-bit scratch
__device__ uint32_t g_xt[MTOT*EMBD];          // x as tf32 [bt][c]
__device__ uint32_t g_wqkv[NQKV*EMBD];        // W as tf32 [n=z*1024+h*64+d][c]
__device__ uint32_t g_wproj[EMBD*EMBD];       // Wproj tf32 [n][j]
__device__ uint32_t g_q[BATCH*NHEAD*SEQ*HDIM];    // prescaled tf32 [b,h,t,d]
__device__ uint32_t g_k[BATCH*NHEAD*SEQ*HDIM];    // tf32 [b,h,t,d]
__device__ uint32_t g_vT[BATCH*NHEAD*HDIM*SEQ];   // tf32 [b,h,d,t]
__device__ uint32_t g_attn[BATCH*NHEAD*SEQ*HDIM]; // tf32 [b,h,t,d]

// ---------------------------------------------------------------------------
__device__ __forceinline__ uint32_t f2tf(float f) {
    uint32_t u; asm("cvt.rna.tf32.f32 %0, %1;" : "=r"(u) : "f"(f)); return u;
}
__device__ __forceinline__ uint32_t smem_u32(const void* p) {
    return (uint32_t)__cvta_generic_to_shared(p);
}
__device__ __forceinline__ void ldsm4(uint32_t* r, uint32_t a) {
    asm volatile("ldmatrix.sync.aligned.m8n8.x4.shared.b16 {%0,%1,%2,%3}, [%4];"
        : "=r"(r[0]), "=r"(r[1]), "=r"(r[2]), "=r"(r[3]) : "r"(a) : "memory");
}
__device__ __forceinline__ void mma8(float* c, const uint32_t* a, uint32_t b0, uint32_t b1) {
    asm volatile("mma.sync.aligned.m16n8k8.row.col.f32.tf32.tf32.f32 "
        "{%0,%1,%2,%3},{%4,%5,%6,%7},{%8,%9},{%0,%1,%2,%3};"
        : "+f"(c[0]), "+f"(c[1]), "+f"(c[2]), "+f"(c[3])
        : "r"(a[0]), "r"(a[1]), "r"(a[2]), "r"(a[3]), "r"(b0), "r"(b1));
}
__device__ __forceinline__ void cp16(uint32_t saddr, const void* g) {
    asm volatile("cp.async.cg.shared.global [%0], [%1], 16;" :: "r"(saddr), "l"(g));
}
#define CP_COMMIT() asm volatile("cp.async.commit_group;")
#define CP_WAIT1()  asm volatile("cp.async.wait_group 1;")
#define CP_WAIT0()  asm volatile("cp.async.wait_group 0;")

// ---------------------------------------------------------------------------
// Convert: fp32 -> tf32 bits, elementwise (float4)
// ---------------------------------------------------------------------------
__global__ __launch_bounds__(256) void cvt_kernel(
    const float4* __restrict__ in, uint4* __restrict__ out, int n4)
{
    int i = blockIdx.x * 256 + threadIdx.x;
    if (i < n4) {
        float4 v = in[i];
        out[i] = make_uint4(f2tf(v.x), f2tf(v.y), f2tf(v.z), f2tf(v.w));
    }
}

// Transpose+convert W{q,k,v}[h][c][d] -> g_wqkv[z*1024+h*64+d][c]
// grid (EMBD/32, HDIM/32, 48), block 256
__global__ __launch_bounds__(256) void wt_kernel(
    const float* __restrict__ Wq, const float* __restrict__ Wk,
    const float* __restrict__ Wv)
{
    __shared__ float tile[32][33];
    const int zh = blockIdx.z;
    const int z = zh >> 4, h = zh & 15;
    const float* W = (z == 0 ? Wq : z == 1 ? Wk : Wv) + (size_t)h * EMBD * HDIM;
    const int c0 = blockIdx.x * 32, d0 = blockIdx.y * 32;
    const int t = threadIdx.x;
    const int r = t >> 3, c4 = (t & 7) * 4;

    float4 v = *(const float4*)&W[(size_t)(c0 + r) * HDIM + d0 + c4];
    tile[r][c4 + 0] = v.x; tile[r][c4 + 1] = v.y;
    tile[r][c4 + 2] = v.z; tile[r][c4 + 3] = v.w;
    __syncthreads();
    // out row n = z*1024 + h*64 + d0 + r, cols c0 + c4 .. +3
    uint4 o = make_uint4(f2tf(tile[c4 + 0][r]), f2tf(tile[c4 + 1][r]),
                         f2tf(tile[c4 + 2][r]), f2tf(tile[c4 + 3][r]));
    *(uint4*)&g_wqkv[(size_t)(z * 1024 + h * 64 + d0 + r) * EMBD + c0 + c4] = o;
}

// ---------------------------------------------------------------------------
// QKV GEMM: C[8192, 3072] = xt @ wqkv^T, scatter to g_q / g_k / g_vT.
// Tile 128x128, BK=32, 2-stage cp.async. grid (64, 24), 256 thr.
// ---------------------------------------------------------------------------
__global__ __launch_bounds__(256, 2) void qkv_kernel()
{
    extern __shared__ uint32_t sm[];
    uint32_t* As = sm;               // [2][128*36]
    uint32_t* Bs = sm + 2 * 128 * 36;

    const int m0 = blockIdx.x * 128, n0 = blockIdx.y * 128;
    const int tid = threadIdx.x;
    const int lane = tid & 31, wid = tid >> 5;
    const int wm = wid & 3, wn = wid >> 2;
    const int lr = lane & 7, ls = lane >> 3;

    float acc[2][8][4];
#pragma unroll
    for (int mt = 0; mt < 2; mt++)
#pragma unroll
        for (int nt = 0; nt < 8; nt++)
#pragma unroll
            for (int c = 0; c < 4; c++) acc[mt][nt][c] = 0.f;

    const int a_row = wm * 32 + lr + ((ls & 1) << 3);
    const int a_k = (ls >> 1) << 2;
    const int b_row = wn * 64 + lr + ((ls >> 1) << 3);
    const int b_k = (ls & 1) << 2;

#define QKV_LOAD(st, k0)                                                      \
    {                                                                         \
        _Pragma("unroll")                                                     \
        for (int it = 0; it < 4; it++) {                                      \
            int idx = tid + it * 256;                                         \
            int r = idx >> 3, c4 = (idx & 7) * 4;                             \
            cp16(smem_u32(&As[(st) * 128 * 36 + r * 36 + c4]),                \
                 &g_xt[(size_t)(m0 + r) * EMBD + (k0) + c4]);                 \
            cp16(smem_u32(&Bs[(st) * 128 * 36 + r * 36 + c4]),                \
                 &g_wqkv[(size_t)(n0 + r) * EMBD + (k0) + c4]);               \
        }                                                                     \
    }

    QKV_LOAD(0, 0); CP_COMMIT();

    for (int kt = 0; kt < 32; kt++) {
        const int cur = kt & 1;
        if (kt < 31) { QKV_LOAD(cur ^ 1, (kt + 1) * 32); CP_COMMIT(); CP_WAIT1(); }
        else CP_WAIT0();
        __syncthreads();
        const uint32_t* A = &As[cur * 128 * 36];
        const uint32_t* B = &Bs[cur * 128 * 36];
#pragma unroll
        for (int kk = 0; kk < 32; kk += 8) {
            uint32_t a[2][4];
            ldsm4(a[0], smem_u32(&A[a_row * 36 + kk + a_k]));
            ldsm4(a[1], smem_u32(&A[(a_row + 16) * 36 + kk + a_k]));
#pragma unroll
            for (int g = 0; g < 4; g++) {
                uint32_t b[4];
                ldsm4(b, smem_u32(&B[(b_row + g * 16) * 36 + kk + b_k]));
                mma8(acc[0][2*g+0], a[0], b[0], b[1]);
                mma8(acc[0][2*g+1], a[0], b[2], b[3]);
                mma8(acc[1][2*g+0], a[1], b[0], b[1]);
                mma8(acc[1][2*g+1], a[1], b[2], b[3]);
            }
        }
        __syncthreads();
    }

    // epilogue: warp n-range is 64-aligned -> z,h fixed per warp
    const int nb = n0 + wn * 64;
    const int zz = nb >> 10, h = (nb >> 6) & 15;
#pragma unroll
    for (int mt = 0; mt < 2; mt++) {
        int row = m0 + wm * 32 + mt * 16 + (lane >> 2);
        int b = row >> 11, t = row & 2047;
#pragma unroll
        for (int nt = 0; nt < 8; nt++) {
            int d = nt * 8 + 2 * (lane & 3);
            float c0f = acc[mt][nt][0], c1f = acc[mt][nt][1];
            float c2f = acc[mt][nt][2], c3f = acc[mt][nt][3];
            if (zz == 0) {
                uint32_t* base = &g_q[(((size_t)(b * NHEAD + h)) * SEQ + t) * HDIM];
                *(uint2*)&base[d] = make_uint2(f2tf(c0f * QK_SCALE_L2), f2tf(c1f * QK_SCALE_L2));
                *(uint2*)&base[8 * HDIM + d] = make_uint2(f2tf(c2f * QK_SCALE_L2), f2tf(c3f * QK_SCALE_L2));
            } else if (zz == 1) {
                uint32_t* base = &g_k[(((size_t)(b * NHEAD + h)) * SEQ + t) * HDIM];
                *(uint2*)&base[d] = make_uint2(f2tf(c0f), f2tf(c1f));
                *(uint2*)&base[8 * HDIM + d] = make_uint2(f2tf(c2f), f2tf(c3f));
            } else {
                uint32_t* base = &g_vT[((size_t)(b * NHEAD + h)) * HDIM * SEQ];
                base[(size_t)(d    ) * SEQ + t    ] = f2tf(c0f);
                base[(size_t)(d + 1) * SEQ + t    ] = f2tf(c1f);
                base[(size_t)(d    ) * SEQ + t + 8] = f2tf(c2f);
                base[(size_t)(d + 1) * SEQ + t + 8] = f2tf(c3f);
            }
        }
    }
#undef QKV_LOAD
}

// ---------------------------------------------------------------------------
// Flash attention: Q tile 128, K/V tiles 64, 2-stage cp.async on K/V.
// grid (16, 64), 256 thr.
// ---------------------------------------------------------------------------
__global__ __launch_bounds__(256) void attn_kernel()
{
    extern __shared__ uint32_t sm[];
    uint32_t* Qs = sm;                      // [128][68]
    uint32_t* Ks = Qs + 128 * 68;           // [2][64][68]
    uint32_t* Vs = Ks + 2 * 64 * 68;        // [2][64][68]  (rows = d, cols = t)
    uint32_t* Ps = Vs + 2 * 64 * 68;        // [128][68]

    const int qt = blockIdx.x, bh = blockIdx.y;
    const int m0 = qt * 128;
    const int tid = threadIdx.x;
    const int lane = tid & 31, wid = tid >> 5;
    const int lr = lane & 7, ls = lane >> 3;

    const uint32_t* qp = g_q + (size_t)bh * SEQ * HDIM;
    const uint32_t* kp = g_k + (size_t)bh * SEQ * HDIM;
    const uint32_t* vp = g_vT + (size_t)bh * HDIM * SEQ;

    // Q load (group 0, with KV stage 0)
#pragma unroll
    for (int it = 0; it < 8; it++) {
        int idx = tid + it * 256;
        int r = idx >> 4, c4 = (idx & 15) * 4;
        cp16(smem_u32(&Qs[r * 68 + c4]), &qp[(size_t)(m0 + r) * HDIM + c4]);
    }
#define KV_LOAD(st, n0_)                                                      \
    {                                                                         \
        _Pragma("unroll")                                                     \
        for (int it = 0; it < 4; it++) {                                      \
            int idx = tid + it * 256;                                         \
            int r = idx >> 4, c4 = (idx & 15) * 4;                            \
            cp16(smem_u32(&Ks[(st) * 64 * 68 + r * 68 + c4]),                 \
                 &kp[(size_t)((n0_) + r) * HDIM + c4]);                       \
            cp16(smem_u32(&Vs[(st) * 64 * 68 + r * 68 + c4]),                 \
                 &vp[(size_t)r * SEQ + (n0_) + c4]);                          \
        }                                                                     \
    }
    KV_LOAD(0, 0); CP_COMMIT();

    float o[8][4];
#pragma unroll
    for (int nt = 0; nt < 8; nt++)
#pragma unroll
        for (int c = 0; c < 4; c++) o[nt][c] = 0.f;
    float mrow[2] = { -INFINITY, -INFINITY };
    float lrow[2] = { 0.f, 0.f };

    const int s_arow = wid * 16 + lr + ((ls & 1) << 3);
    const int s_akof = (ls >> 1) << 2;
    const int s_brow = lr + ((ls >> 1) << 3);
    const int s_bkof = (ls & 1) << 2;

    const int jtmax = 2 * qt + 1;
    for (int jt = 0; jt <= jtmax; jt++) {
        const int cur = jt & 1;
        if (jt < jtmax) { KV_LOAD(cur ^ 1, (jt + 1) * 64); CP_COMMIT(); CP_WAIT1(); }
        else CP_WAIT0();
        __syncthreads();
        const uint32_t* K = &Ks[cur * 64 * 68];
        const uint32_t* V = &Vs[cur * 64 * 68];

        // S = Q K^T
        float s[8][4];
#pragma unroll
        for (int nt = 0; nt < 8; nt++)
#pragma unroll
            for (int c = 0; c < 4; c++) s[nt][c] = 0.f;
#pragma unroll
        for (int kk = 0; kk < 64; kk += 8) {
            uint32_t a[4];
            ldsm4(a, smem_u32(&Qs[s_arow * 68 + kk + s_akof]));
#pragma unroll
            for (int g = 0; g < 4; g++) {
                uint32_t b[4];
                ldsm4(b, smem_u32(&K[(g * 16 + s_brow) * 68 + kk + s_bkof]));
                mma8(s[2*g+0], a, b[0], b[1]);
                mma8(s[2*g+1], a, b[2], b[3]);
            }
        }

        const int grow = m0 + wid * 16 + (lane >> 2);
        if (jt >= 2 * qt) {
            const int n0 = jt * 64;
#pragma unroll
            for (int nt = 0; nt < 8; nt++) {
                int col = n0 + nt * 8 + 2 * (lane & 3);
                if (col     > grow)     s[nt][0] = -INFINITY;
                if (col + 1 > grow)     s[nt][1] = -INFINITY;
                if (col     > grow + 8) s[nt][2] = -INFINITY;
                if (col + 1 > grow + 8) s[nt][3] = -INFINITY;
            }
        }

        // online softmax (log2 domain; scale folded into Q)
        float mx0 = -INFINITY, mx1 = -INFINITY;
#pragma unroll
        for (int nt = 0; nt < 8; nt++) {
            mx0 = fmaxf(mx0, fmaxf(s[nt][0], s[nt][1]));
            mx1 = fmaxf(mx1, fmaxf(s[nt][2], s[nt][3]));
        }
        mx0 = fmaxf(mx0, __shfl_xor_sync(0xffffffffu, mx0, 1));
        mx0 = fmaxf(mx0, __shfl_xor_sync(0xffffffffu, mx0, 2));
        mx1 = fmaxf(mx1, __shfl_xor_sync(0xffffffffu, mx1, 1));
        mx1 = fmaxf(mx1, __shfl_xor_sync(0xffffffffu, mx1, 2));
        float mn0 = fmaxf(mrow[0], mx0), mn1 = fmaxf(mrow[1], mx1);
        float al0 = exp2f(mrow[0] - mn0), al1 = exp2f(mrow[1] - mn1);
        float rs0 = 0.f, rs1 = 0.f;
#pragma unroll
        for (int nt = 0; nt < 8; nt++) {
            s[nt][0] = exp2f(s[nt][0] - mn0); rs0 += s[nt][0];
            s[nt][1] = exp2f(s[nt][1] - mn0); rs0 += s[nt][1];
            s[nt][2] = exp2f(s[nt][2] - mn1); rs1 += s[nt][2];
            s[nt][3] = exp2f(s[nt][3] - mn1); rs1 += s[nt][3];
        }
        rs0 += __shfl_xor_sync(0xffffffffu, rs0, 1);
        rs0 += __shfl_xor_sync(0xffffffffu, rs0, 2);
        rs1 += __shfl_xor_sync(0xffffffffu, rs1, 1);
        rs1 += __shfl_xor_sync(0xffffffffu, rs1, 2);
        lrow[0] = lrow[0] * al0 + rs0; mrow[0] = mn0;
        lrow[1] = lrow[1] * al1 + rs1; mrow[1] = mn1;
#pragma unroll
        for (int nt = 0; nt < 8; nt++) {
            o[nt][0] *= al0; o[nt][1] *= al0;
            o[nt][2] *= al1; o[nt][3] *= al1;
        }

        // P -> smem (warp-private strip)
        {
            int pr = wid * 16 + (lane >> 2);
#pragma unroll
            for (int nt = 0; nt < 8; nt++) {
                int col = nt * 8 + 2 * (lane & 3);
                *(uint2*)&Ps[pr * 68 + col]       = make_uint2(f2tf(s[nt][0]), f2tf(s[nt][1]));
                *(uint2*)&Ps[(pr + 8) * 68 + col] = make_uint2(f2tf(s[nt][2]), f2tf(s[nt][3]));
            }
        }
        __syncwarp();

        // O += P @ V
#pragma unroll
        for (int kk = 0; kk < 64; kk += 8) {
            uint32_t a[4];
            ldsm4(a, smem_u32(&Ps[s_arow * 68 + kk + s_akof]));
#pragma unroll
            for (int g = 0; g < 4; g++) {
                uint32_t b[4];
                ldsm4(b, smem_u32(&V[(g * 16 + s_brow) * 68 + kk + s_bkof]));
                mma8(o[2*g+0], a, b[0], b[1]);
                mma8(o[2*g+1], a, b[2], b[3]);
            }
        }
        __syncthreads();
    }

    // epilogue: store tf32 bits to g_attn
    {
        float inv0 = 1.f / lrow[0], inv1 = 1.f / lrow[1];
        int row = m0 + wid * 16 + (lane >> 2);
        uint32_t* op = g_attn + ((size_t)bh * SEQ + row) * HDIM;
#pragma unroll
        for (int nt = 0; nt < 8; nt++) {
            int col = nt * 8 + 2 * (lane & 3);
            *(uint2*)&op[col] = make_uint2(f2tf(o[nt][0] * inv0), f2tf(o[nt][1] * inv0));
            *(uint2*)&op[8 * HDIM + col] = make_uint2(f2tf(o[nt][2] * inv1), f2tf(o[nt][3] * inv1));
        }
    }
#undef KV_LOAD
}

// ---------------------------------------------------------------------------
// Output projection: out[8192,1024] = attn @ wproj^T + bias.
// Tile 128x128, BK=32, 2-stage. grid (64, 8), 256 thr.
// ---------------------------------------------------------------------------
__global__ __launch_bounds__(256, 2) void proj_kernel(
    const float* __restrict__ bproj, float* __restrict__ out)
{
    extern __shared__ uint32_t sm[];
    uint32_t* As = sm;
    uint32_t* Bs = sm + 2 * 128 * 36;

    const int m0 = blockIdx.x * 128, n0 = blockIdx.y * 128;
    const int tid = threadIdx.x;
    const int lane = tid & 31, wid = tid >> 5;
    const int wm = wid & 3, wn = wid >> 2;
    const int lr = lane & 7, ls = lane >> 3;

    float acc[2][8][4];
#pragma unroll
    for (int mt = 0; mt < 2; mt++)
#pragma unroll
        for (int nt = 0; nt < 8; nt++)
#pragma unroll
            for (int c = 0; c < 4; c++) acc[mt][nt][c] = 0.f;

    const int a_row = wm * 32 + lr + ((ls & 1) << 3);
    const int a_k = (ls >> 1) << 2;
    const int b_row = wn * 64 + lr + ((ls >> 1) << 3);
    const int b_k = (ls & 1) << 2;

#define PROJ_LOAD(st, k0)                                                     \
    {                                                                         \
        const int h_ = (k0) >> 6, doff_ = (k0) & 63;                          \
        _Pragma("unroll")                                                     \
        for (int it = 0; it < 4; it++) {                                      \
            int idx = tid + it * 256;                                         \
            int r = idx >> 3, c4 = (idx & 7) * 4;                             \
            int bt = m0 + r, b_ = bt >> 11, t_ = bt & 2047;                   \
            cp16(smem_u32(&As[(st) * 128 * 36 + r * 36 + c4]),                \
                 &g_attn[(((size_t)(b_ * NHEAD + h_)) * SEQ + t_) * HDIM + doff_ + c4]); \
            cp16(smem_u32(&Bs[(st) * 128 * 36 + r * 36 + c4]),                \
                 &g_wproj[(size_t)(n0 + r) * EMBD + (k0) + c4]);              \
        }                                                                     \
    }

    PROJ_LOAD(0, 0); CP_COMMIT();

    for (int kt = 0; kt < 32; kt++) {
        const int cur = kt & 1;
        if (kt < 31) { PROJ_LOAD(cur ^ 1, (kt + 1) * 32); CP_COMMIT(); CP_WAIT1(); }
        else CP_WAIT0();
        __syncthreads();
        const uint32_t* A = &As[cur * 128 * 36];
        const uint32_t* B = &Bs[cur * 128 * 36];
#pragma unroll
        for (int kk = 0; kk < 32; kk += 8) {
            uint32_t a[2][4];
            ldsm4(a[0], smem_u32(&A[a_row * 36 + kk + a_k]));
            ldsm4(a[1], smem_u32(&A[(a_row + 16) * 36 + kk + a_k]));
#pragma unroll
            for (int g = 0; g < 4; g++) {
                uint32_t b[4];
                ldsm4(b, smem_u32(&B[(b_row + g * 16) * 36 + kk + b_k]));
                mma8(acc[0][2*g+0], a[0], b[0], b[1]);
                mma8(acc[0][2*g+1], a[0], b[2], b[3]);
                mma8(acc[1][2*g+0], a[1], b[0], b[1]);
                mma8(acc[1][2*g+1], a[1], b[2], b[3]);
            }
        }
        __syncthreads();
    }

#pragma unroll
    for (int mt = 0; mt < 2; mt++) {
        int row = m0 + wm * 32 + mt * 16 + (lane >> 2);
        float* o0 = out + (size_t)row * EMBD;
        float* o1 = out + (size_t)(row + 8) * EMBD;
#pragma unroll
        for (int nt = 0; nt < 8; nt++) {
            int col = n0 + wn * 64 + nt * 8 + 2 * (lane & 3);
            float b0 = bproj[col], b1 = bproj[col + 1];
            *(float2*)&o0[col] = make_float2(acc[mt][nt][0] + b0, acc[mt][nt][1] + b1);
            *(float2*)&o1[col] = make_float2(acc[mt][nt][2] + b0, acc[mt][nt][3] + b1);
        }
    }
#undef PROJ_LOAD
}

// ---------------------------------------------------------------------------
extern "C" void kernel_launch(void* const* d_in, const int* in_sizes, int n_in,
                              void* d_out, int out_size)
{
    const float* x     = (const float*)d_in[0];
    const float* Wq    = (const float*)d_in[1];
    const float* Wk    = (const float*)d_in[2];
    const float* Wv    = (const float*)d_in[3];
    const float* Wproj = (const float*)d_in[4];
    const float* bproj = (const float*)d_in[5];
    float* out = (float*)d_out;

    uint32_t* xt_p;     cudaGetSymbolAddress((void**)&xt_p, g_xt);
    uint32_t* wproj_p;  cudaGetSymbolAddress((void**)&wproj_p, g_wproj);

    // conversions
    cvt_kernel<<<(MTOT * EMBD / 4 + 255) / 256, 256>>>(
        (const float4*)x, (uint4*)xt_p, MTOT * EMBD / 4);
    cvt_kernel<<<(EMBD * EMBD / 4 + 255) / 256, 256>>>(
        (const float4*)Wproj, (uint4*)wproj_p, EMBD * EMBD / 4);
    wt_kernel<<<dim3(EMBD / 32, HDIM / 32, 48), 256>>>(Wq, Wk, Wv);

    const int gemm_smem = 4 * 128 * 36 * (int)sizeof(uint32_t);  // 73728
    cudaFuncSetAttribute(qkv_kernel, cudaFuncAttributeMaxDynamicSharedMemorySize, gemm_smem);
    cudaFuncSetAttribute(proj_kernel, cudaFuncAttributeMaxDynamicSharedMemorySize, gemm_smem);

    qkv_kernel<<<dim3(MTOT / 128, NQKV / 128), 256, gemm_smem>>>();

    const int attn_smem = (128*68 + 2*64*68 + 2*64*68 + 128*68) * (int)sizeof(uint32_t);
    cudaFuncSetAttribute(attn_kernel, cudaFuncAttributeMaxDynamicSharedMemorySize, attn_smem);
    attn_kernel<<<dim3(SEQ / 128, BATCH * NHEAD), 256, attn_smem>>>();

    proj_kernel<<<dim3(MTOT / 128, EMBD / 128), 256, gemm_smem>>>(bproj, out);
}

// round 5
// speedup vs baseline: 7.1605x; 1.9058x over previous
#include <cuda_runtime.h>
#include <cuda_fp16.h>
#include <math.h>
#include <stdint.h>

#define BATCH 4
#define SEQ   2048
#define EMBD  1024
#define NHEAD 16
#define HDIM  64
#define MTOT  (BATCH*SEQ)            // 8192
#define NQKV  (3*NHEAD*HDIM)         // 3072
#define QK_SCALE_L2 (0.03125f * 1.44269504088896340736f)

// fp16 scratch
__device__ __half g_xt[MTOT*EMBD];
__device__ __half g_wqkv[NQKV*EMBD];
__device__ __half g_wproj[EMBD*EMBD];
__device__ __half g_q[BATCH*NHEAD*SEQ*HDIM];
__device__ __half g_k[BATCH*NHEAD*SEQ*HDIM];
__device__ __half g_vT[BATCH*NHEAD*HDIM*SEQ];
__device__ __half g_attn[BATCH*NHEAD*SEQ*HDIM];

// ---------------------------------------------------------------------------
__device__ __forceinline__ uint32_t smem_u32(const void* p) {
    return (uint32_t)__cvta_generic_to_shared(p);
}
__device__ __forceinline__ void ldsm4(uint32_t* r, uint32_t a) {
    asm volatile("ldmatrix.sync.aligned.m8n8.x4.shared.b16 {%0,%1,%2,%3}, [%4];"
        : "=r"(r[0]), "=r"(r[1]), "=r"(r[2]), "=r"(r[3]) : "r"(a) : "memory");
}
__device__ __forceinline__ void mma16(float* c, const uint32_t* a, uint32_t b0, uint32_t b1) {
    asm volatile("mma.sync.aligned.m16n8k16.row.col.f32.f16.f16.f32 "
        "{%0,%1,%2,%3},{%4,%5,%6,%7},{%8,%9},{%0,%1,%2,%3};"
        : "+f"(c[0]), "+f"(c[1]), "+f"(c[2]), "+f"(c[3])
        : "r"(a[0]), "r"(a[1]), "r"(a[2]), "r"(a[3]), "r"(b0), "r"(b1));
}
__device__ __forceinline__ void cp16(uint32_t saddr, const void* g) {
    asm volatile("cp.async.cg.shared.global [%0], [%1], 16;" :: "r"(saddr), "l"(g));
}
#define CP_COMMIT() asm volatile("cp.async.commit_group;")
#define CP_WAIT1()  asm volatile("cp.async.wait_group 1;")
#define CP_WAIT0()  asm volatile("cp.async.wait_group 0;")

__device__ __forceinline__ uint32_t pack_h2(float a, float b) {
    __half2 h = __floats2half2_rn(a, b);
    return *reinterpret_cast<uint32_t*>(&h);
}

// ---------------------------------------------------------------------------
__global__ __launch_bounds__(256) void cvt_kernel(
    const float4* __restrict__ in, uint2* __restrict__ out, int n4)
{
    int i = blockIdx.x * 256 + threadIdx.x;
    if (i < n4) {
        float4 v = in[i];
        out[i] = make_uint2(pack_h2(v.x, v.y), pack_h2(v.z, v.w));
    }
}

__global__ __launch_bounds__(256) void wt_kernel(
    const float* __restrict__ Wq, const float* __restrict__ Wk,
    const float* __restrict__ Wv)
{
    __shared__ float tile[32][33];
    const int zh = blockIdx.z;
    const int z = zh >> 4, h = zh & 15;
    const float* W = (z == 0 ? Wq : z == 1 ? Wk : Wv) + (size_t)h * EMBD * HDIM;
    const int c0 = blockIdx.x * 32, d0 = blockIdx.y * 32;
    const int t = threadIdx.x;
    const int r = t >> 3, c4 = (t & 7) * 4;

    float4 v = *(const float4*)&W[(size_t)(c0 + r) * HDIM + d0 + c4];
    tile[r][c4 + 0] = v.x; tile[r][c4 + 1] = v.y;
    tile[r][c4 + 2] = v.z; tile[r][c4 + 3] = v.w;
    __syncthreads();
    uint2 o = make_uint2(pack_h2(tile[c4 + 0][r], tile[c4 + 1][r]),
                         pack_h2(tile[c4 + 2][r], tile[c4 + 3][r]));
    *(uint2*)&g_wqkv[(size_t)(z * 1024 + h * 64 + d0 + r) * EMBD + c0 + c4] = o;
}

// ---------------------------------------------------------------------------
// QKV GEMM: C[8192,3072] = xt @ wqkv^T -> g_q / g_k / g_vT.
// Tile 128x128, BK=64 fp16, 2-stage cp.async. grid (64,24), 256 thr.
// ---------------------------------------------------------------------------
#define ASZ (128*72)
__global__ __launch_bounds__(256, 2) void qkv_kernel()
{
    extern __shared__ __half sm[];
    __half* As = sm;                  // [2][128*72]
    __half* Bs = sm + 2 * ASZ;

    const int m0 = blockIdx.x * 128, n0 = blockIdx.y * 128;
    const int tid = threadIdx.x;
    const int lane = tid & 31, wid = tid >> 5;
    const int wm = wid & 3, wn = wid >> 2;
    const int lr = lane & 7, ls = lane >> 3;

    float acc[2][8][4];
#pragma unroll
    for (int mt = 0; mt < 2; mt++)
#pragma unroll
        for (int nt = 0; nt < 8; nt++)
#pragma unroll
            for (int c = 0; c < 4; c++) acc[mt][nt][c] = 0.f;

    const int a_row = wm * 32 + (lane & 15);
    const int a_k = (ls >> 1) * 8;
    const int b_row = wn * 64 + lr + ((ls >> 1) << 3);
    const int b_k = (ls & 1) * 8;

    // 128 rows x 64 halves per tile: 8 x cp16 per row -> 1024 ops -> 4 iters
#define QKV_LOAD(st, k0)                                                      \
    {                                                                         \
        _Pragma("unroll")                                                     \
        for (int it = 0; it < 4; it++) {                                      \
            int idx = tid + it * 256;                                         \
            int r = idx >> 3, ch = (idx & 7) * 8;                             \
            cp16(smem_u32(&As[(st) * ASZ + r * 72 + ch]),                     \
                 &g_xt[(size_t)(m0 + r) * EMBD + (k0) + ch]);                 \
            cp16(smem_u32(&Bs[(st) * ASZ + r * 72 + ch]),                     \
                 &g_wqkv[(size_t)(n0 + r) * EMBD + (k0) + ch]);               \
        }                                                                     \
    }

    QKV_LOAD(0, 0); CP_COMMIT();

    for (int kt = 0; kt < 16; kt++) {
        const int cur = kt & 1;
        if (kt < 15) { QKV_LOAD(cur ^ 1, (kt + 1) * 64); CP_COMMIT(); CP_WAIT1(); }
        else CP_WAIT0();
        __syncthreads();
        const __half* A = &As[cur * ASZ];
        const __half* B = &Bs[cur * ASZ];
#pragma unroll
        for (int kk = 0; kk < 64; kk += 16) {
            uint32_t a[2][4];
            ldsm4(a[0], smem_u32(&A[a_row * 72 + kk + a_k]));
            ldsm4(a[1], smem_u32(&A[(a_row + 16) * 72 + kk + a_k]));
#pragma unroll
            for (int g = 0; g < 4; g++) {
                uint32_t b[4];
                ldsm4(b, smem_u32(&B[(b_row + g * 16) * 72 + kk + b_k]));
                mma16(acc[0][2*g+0], a[0], b[0], b[1]);
                mma16(acc[0][2*g+1], a[0], b[2], b[3]);
                mma16(acc[1][2*g+0], a[1], b[0], b[1]);
                mma16(acc[1][2*g+1], a[1], b[2], b[3]);
            }
        }
        __syncthreads();
    }

    const int nb = n0 + wn * 64;
    const int zz = nb >> 10, h = (nb >> 6) & 15;
#pragma unroll
    for (int mt = 0; mt < 2; mt++) {
        int row = m0 + wm * 32 + mt * 16 + (lane >> 2);
        int b = row >> 11, t = row & 2047;
#pragma unroll
        for (int nt = 0; nt < 8; nt++) {
            int d = nt * 8 + 2 * (lane & 3);
            float c0f = acc[mt][nt][0], c1f = acc[mt][nt][1];
            float c2f = acc[mt][nt][2], c3f = acc[mt][nt][3];
            if (zz == 0) {
                __half* base = &g_q[(((size_t)(b * NHEAD + h)) * SEQ + t) * HDIM];
                *(uint32_t*)&base[d] = pack_h2(c0f * QK_SCALE_L2, c1f * QK_SCALE_L2);
                *(uint32_t*)&base[8 * HDIM + d] = pack_h2(c2f * QK_SCALE_L2, c3f * QK_SCALE_L2);
            } else if (zz == 1) {
                __half* base = &g_k[(((size_t)(b * NHEAD + h)) * SEQ + t) * HDIM];
                *(uint32_t*)&base[d] = pack_h2(c0f, c1f);
                *(uint32_t*)&base[8 * HDIM + d] = pack_h2(c2f, c3f);
            } else {
                __half* base = &g_vT[((size_t)(b * NHEAD + h)) * HDIM * SEQ];
                base[(size_t)(d    ) * SEQ + t    ] = __float2half_rn(c0f);
                base[(size_t)(d + 1) * SEQ + t    ] = __float2half_rn(c1f);
                base[(size_t)(d    ) * SEQ + t + 8] = __float2half_rn(c2f);
                base[(size_t)(d + 1) * SEQ + t + 8] = __float2half_rn(c3f);
            }
        }
    }
#undef QKV_LOAD
}

// ---------------------------------------------------------------------------
// Flash attention fp16: Q tile 128, K/V tiles 64, 2-stage cp.async.
// grid (16,64), 256 thr. smem 72KB -> 2 CTA/SM.
// ---------------------------------------------------------------------------
#define KSZ (64*72)
__global__ __launch_bounds__(256, 2) void attn_kernel()
{
    extern __shared__ __half sm[];
    __half* Qs = sm;                      // [128][72]
    __half* Ks = Qs + 128 * 72;           // [2][64][72]
    __half* Vs = Ks + 2 * KSZ;            // [2][64][72] rows = d, cols = t
    __half* Ps = Vs + 2 * KSZ;            // [128][72]

    const int qt = blockIdx.x, bh = blockIdx.y;
    const int m0 = qt * 128;
    const int tid = threadIdx.x;
    const int lane = tid & 31, wid = tid >> 5;
    const int lr = lane & 7, ls = lane >> 3;

    const __half* qp = g_q + (size_t)bh * SEQ * HDIM;
    const __half* kp = g_k + (size_t)bh * SEQ * HDIM;
    const __half* vp = g_vT + (size_t)bh * HDIM * SEQ;

    // Q: 128 rows x 64 halves -> 1024 cp16 -> 4 iters
#pragma unroll
    for (int it = 0; it < 4; it++) {
        int idx = tid + it * 256;
        int r = idx >> 3, ch = (idx & 7) * 8;
        cp16(smem_u32(&Qs[r * 72 + ch]), &qp[(size_t)(m0 + r) * HDIM + ch]);
    }
    // K/V: 64 rows x 64 halves each -> 512 cp16 each -> 2 iters combined
#define KV_LOAD(st, n0_)                                                      \
    {                                                                         \
        _Pragma("unroll")                                                     \
        for (int it = 0; it < 2; it++) {                                      \
            int idx = tid + it * 256;                                         \
            int r = idx >> 3, ch = (idx & 7) * 8;                             \
            cp16(smem_u32(&Ks[(st) * KSZ + r * 72 + ch]),                     \
                 &kp[(size_t)((n0_) + r) * HDIM + ch]);                       \
            cp16(smem_u32(&Vs[(st) * KSZ + r * 72 + ch]),                     \
                 &vp[(size_t)r * SEQ + (n0_) + ch]);                          \
        }                                                                     \
    }
    KV_LOAD(0, 0); CP_COMMIT();

    float o[8][4];
#pragma unroll
    for (int nt = 0; nt < 8; nt++)
#pragma unroll
        for (int c = 0; c < 4; c++) o[nt][c] = 0.f;
    float mrow[2] = { -INFINITY, -INFINITY };
    float lrow[2] = { 0.f, 0.f };

    const int s_arow = wid * 16 + (lane & 15);
    const int s_ak = (ls >> 1) * 8;
    const int s_brow = lr + ((ls >> 1) << 3);
    const int s_bk = (ls & 1) * 8;

    const int jtmax = 2 * qt + 1;
    for (int jt = 0; jt <= jtmax; jt++) {
        const int cur = jt & 1;
        if (jt < jtmax) { KV_LOAD(cur ^ 1, (jt + 1) * 64); CP_COMMIT(); CP_WAIT1(); }
        else CP_WAIT0();
        __syncthreads();
        const __half* K = &Ks[cur * KSZ];
        const __half* V = &Vs[cur * KSZ];

        float s[8][4];
#pragma unroll
        for (int nt = 0; nt < 8; nt++)
#pragma unroll
            for (int c = 0; c < 4; c++) s[nt][c] = 0.f;
#pragma unroll
        for (int kk = 0; kk < 64; kk += 16) {
            uint32_t a[4];
            ldsm4(a, smem_u32(&Qs[s_arow * 72 + kk + s_ak]));
#pragma unroll
            for (int g = 0; g < 4; g++) {
                uint32_t b[4];
                ldsm4(b, smem_u32(&K[(g * 16 + s_brow) * 72 + kk + s_bk]));
                mma16(s[2*g+0], a, b[0], b[1]);
                mma16(s[2*g+1], a, b[2], b[3]);
            }
        }

        const int grow = m0 + wid * 16 + (lane >> 2);
        if (jt >= 2 * qt) {
            const int n0 = jt * 64;
#pragma unroll
            for (int nt = 0; nt < 8; nt++) {
                int col = n0 + nt * 8 + 2 * (lane & 3);
                if (col     > grow)     s[nt][0] = -INFINITY;
                if (col + 1 > grow)     s[nt][1] = -INFINITY;
                if (col     > grow + 8) s[nt][2] = -INFINITY;
                if (col + 1 > grow + 8) s[nt][3] = -INFINITY;
            }
        }

        float mx0 = -INFINITY, mx1 = -INFINITY;
#pragma unroll
        for (int nt = 0; nt < 8; nt++) {
            mx0 = fmaxf(mx0, fmaxf(s[nt][0], s[nt][1]));
            mx1 = fmaxf(mx1, fmaxf(s[nt][2], s[nt][3]));
        }
        mx0 = fmaxf(mx0, __shfl_xor_sync(0xffffffffu, mx0, 1));
        mx0 = fmaxf(mx0, __shfl_xor_sync(0xffffffffu, mx0, 2));
        mx1 = fmaxf(mx1, __shfl_xor_sync(0xffffffffu, mx1, 1));
        mx1 = fmaxf(mx1, __shfl_xor_sync(0xffffffffu, mx1, 2));
        float mn0 = fmaxf(mrow[0], mx0), mn1 = fmaxf(mrow[1], mx1);
        float al0 = exp2f(mrow[0] - mn0), al1 = exp2f(mrow[1] - mn1);
        float rs0 = 0.f, rs1 = 0.f;
#pragma unroll
        for (int nt = 0; nt < 8; nt++) {
            s[nt][0] = exp2f(s[nt][0] - mn0); rs0 += s[nt][0];
            s[nt][1] = exp2f(s[nt][1] - mn0); rs0 += s[nt][1];
            s[nt][2] = exp2f(s[nt][2] - mn1); rs1 += s[nt][2];
            s[nt][3] = exp2f(s[nt][3] - mn1); rs1 += s[nt][3];
        }
        rs0 += __shfl_xor_sync(0xffffffffu, rs0, 1);
        rs0 += __shfl_xor_sync(0xffffffffu, rs0, 2);
        rs1 += __shfl_xor_sync(0xffffffffu, rs1, 1);
        rs1 += __shfl_xor_sync(0xffffffffu, rs1, 2);
        lrow[0] = lrow[0] * al0 + rs0; mrow[0] = mn0;
        lrow[1] = lrow[1] * al1 + rs1; mrow[1] = mn1;
#pragma unroll
        for (int nt = 0; nt < 8; nt++) {
            o[nt][0] *= al0; o[nt][1] *= al0;
            o[nt][2] *= al1; o[nt][3] *= al1;
        }

        {
            int pr = wid * 16 + (lane >> 2);
#pragma unroll
            for (int nt = 0; nt < 8; nt++) {
                int col = nt * 8 + 2 * (lane & 3);
                *(uint32_t*)&Ps[pr * 72 + col]       = pack_h2(s[nt][0], s[nt][1]);
                *(uint32_t*)&Ps[(pr + 8) * 72 + col] = pack_h2(s[nt][2], s[nt][3]);
            }
        }
        __syncwarp();

#pragma unroll
        for (int kk = 0; kk < 64; kk += 16) {
            uint32_t a[4];
            ldsm4(a, smem_u32(&Ps[s_arow * 72 + kk + s_ak]));
#pragma unroll
            for (int g = 0; g < 4; g++) {
                uint32_t b[4];
                ldsm4(b, smem_u32(&V[(g * 16 + s_brow) * 72 + kk + s_bk]));
                mma16(o[2*g+0], a, b[0], b[1]);
                mma16(o[2*g+1], a, b[2], b[3]);
            }
        }
        __syncthreads();
    }

    {
        float inv0 = 1.f / lrow[0], inv1 = 1.f / lrow[1];
        int row = m0 + wid * 16 + (lane >> 2);
        __half* op = g_attn + ((size_t)bh * SEQ + row) * HDIM;
#pragma unroll
        for (int nt = 0; nt < 8; nt++) {
            int col = nt * 8 + 2 * (lane & 3);
            *(uint32_t*)&op[col] = pack_h2(o[nt][0] * inv0, o[nt][1] * inv0);
            *(uint32_t*)&op[8 * HDIM + col] = pack_h2(o[nt][2] * inv1, o[nt][3] * inv1);
        }
    }
#undef KV_LOAD
}

// ---------------------------------------------------------------------------
// Output projection: out[8192,1024] = attn @ wproj^T + bias (fp32 out).
// Tile 128x128, BK=64, 2-stage. grid (64,8), 256 thr.
// ---------------------------------------------------------------------------
__global__ __launch_bounds__(256, 2) void proj_kernel(
    const float* __restrict__ bproj, float* __restrict__ out)
{
    extern __shared__ __half sm[];
    __half* As = sm;
    __half* Bs = sm + 2 * ASZ;

    const int m0 = blockIdx.x * 128, n0 = blockIdx.y * 128;
    const int tid = threadIdx.x;
    const int lane = tid & 31, wid = tid >> 5;
    const int wm = wid & 3, wn = wid >> 2;
    const int lr = lane & 7, ls = lane >> 3;

    float acc[2][8][4];
#pragma unroll
    for (int mt = 0; mt < 2; mt++)
#pragma unroll
        for (int nt = 0; nt < 8; nt++)
#pragma unroll
            for (int c = 0; c < 4; c++) acc[mt][nt][c] = 0.f;

    const int a_row = wm * 32 + (lane & 15);
    const int a_k = (ls >> 1) * 8;
    const int b_row = wn * 64 + lr + ((ls >> 1) << 3);
    const int b_k = (ls & 1) * 8;

    // k-tile kt selects head h=kt; 128 rows x 64 halves -> 4 iters
#define PROJ_LOAD(st, kt_)                                                    \
    {                                                                         \
        _Pragma("unroll")                                                     \
        for (int it = 0; it < 4; it++) {                                      \
            int idx = tid + it * 256;                                         \
            int r = idx >> 3, ch = (idx & 7) * 8;                             \
            int bt = m0 + r, b_ = bt >> 11, t_ = bt & 2047;                   \
            cp16(smem_u32(&As[(st) * ASZ + r * 72 + ch]),                     \
                 &g_attn[(((size_t)(b_ * NHEAD + (kt_))) * SEQ + t_) * HDIM + ch]); \
            cp16(smem_u32(&Bs[(st) * ASZ + r * 72 + ch]),                     \
                 &g_wproj[(size_t)(n0 + r) * EMBD + (kt_) * 64 + ch]);        \
        }                                                                     \
    }

    PROJ_LOAD(0, 0); CP_COMMIT();

    for (int kt = 0; kt < 16; kt++) {
        const int cur = kt & 1;
        if (kt < 15) { PROJ_LOAD(cur ^ 1, kt + 1); CP_COMMIT(); CP_WAIT1(); }
        else CP_WAIT0();
        __syncthreads();
        const __half* A = &As[cur * ASZ];
        const __half* B = &Bs[cur * ASZ];
#pragma unroll
        for (int kk = 0; kk < 64; kk += 16) {
            uint32_t a[2][4];
            ldsm4(a[0], smem_u32(&A[a_row * 72 + kk + a_k]));
            ldsm4(a[1], smem_u32(&A[(a_row + 16) * 72 + kk + a_k]));
#pragma unroll
            for (int g = 0; g < 4; g++) {
                uint32_t b[4];
                ldsm4(b, smem_u32(&B[(b_row + g * 16) * 72 + kk + b_k]));
                mma16(acc[0][2*g+0], a[0], b[0], b[1]);
                mma16(acc[0][2*g+1], a[0], b[2], b[3]);
                mma16(acc[1][2*g+0], a[1], b[0], b[1]);
                mma16(acc[1][2*g+1], a[1], b[2], b[3]);
            }
        }
        __syncthreads();
    }

#pragma unroll
    for (int mt = 0; mt < 2; mt++) {
        int row = m0 + wm * 32 + mt * 16 + (lane >> 2);
        float* o0 = out + (size_t)row * EMBD;
        float* o1 = out + (size_t)(row + 8) * EMBD;
#pragma unroll
        for (int nt = 0; nt < 8; nt++) {
            int col = n0 + wn * 64 + nt * 8 + 2 * (lane & 3);
            float b0 = bproj[col], b1 = bproj[col + 1];
            *(float2*)&o0[col] = make_float2(acc[mt][nt][0] + b0, acc[mt][nt][1] + b1);
            *(float2*)&o1[col] = make_float2(acc[mt][nt][2] + b0, acc[mt][nt][3] + b1);
        }
    }
#undef PROJ_LOAD
}

// ---------------------------------------------------------------------------
extern "C" void kernel_launch(void* const* d_in, const int* in_sizes, int n_in,
                              void* d_out, int out_size)
{
    const float* x     = (const float*)d_in[0];
    const float* Wq    = (const float*)d_in[1];
    const float* Wk    = (const float*)d_in[2];
    const float* Wv    = (const float*)d_in[3];
    const float* Wproj = (const float*)d_in[4];
    const float* bproj = (const float*)d_in[5];
    float* out = (float*)d_out;

    __half* xt_p;     cudaGetSymbolAddress((void**)&xt_p, g_xt);
    __half* wproj_p;  cudaGetSymbolAddress((void**)&wproj_p, g_wproj);

    cvt_kernel<<<(MTOT * EMBD / 4 + 255) / 256, 256>>>(
        (const float4*)x, (uint2*)xt_p, MTOT * EMBD / 4);
    cvt_kernel<<<(EMBD * EMBD / 4 + 255) / 256, 256>>>(
        (const float4*)Wproj, (uint2*)wproj_p, EMBD * EMBD / 4);
    wt_kernel<<<dim3(EMBD / 32, HDIM / 32, 48), 256>>>(Wq, Wk, Wv);

    const int gemm_smem = 4 * ASZ * (int)sizeof(__half);    // 73728
    cudaFuncSetAttribute(qkv_kernel, cudaFuncAttributeMaxDynamicSharedMemorySize, gemm_smem);
    cudaFuncSetAttribute(proj_kernel, cudaFuncAttributeMaxDynamicSharedMemorySize, gemm_smem);

    qkv_kernel<<<dim3(MTOT / 128, NQKV / 128), 256, gemm_smem>>>();

    const int attn_smem = (128*72 + 2*KSZ + 2*KSZ + 128*72) * (int)sizeof(__half); // 73728
    cudaFuncSetAttribute(attn_kernel, cudaFuncAttributeMaxDynamicSharedMemorySize, attn_smem);
    attn_kernel<<<dim3(SEQ / 128, BATCH * NHEAD), 256, attn_smem>>>();

    proj_kernel<<<dim3(MTOT / 128, EMBD / 128), 256, gemm_smem>>>(bproj, out);
}

// round 7
// speedup vs baseline: 8.1470x; 1.1378x over previous
#include <cuda_runtime.h>
#include <cuda_fp16.h>
#include <math.h>
#include <stdint.h>

#define BATCH 4
#define SEQ   2048
#define EMBD  1024
#define NHEAD 16
#define HDIM  64
#define MTOT  (BATCH*SEQ)            // 8192
#define NQKV  (3*NHEAD*HDIM)         // 3072
#define QK_SCALE_L2 (0.03125f * 1.44269504088896340736f)

// fp16 scratch
__device__ __half g_xt[MTOT*EMBD];
__device__ __half g_wqkv[NQKV*EMBD];            // [n][c], n = z*1024+h*64+d
__device__ __half g_wproj[EMBD*EMBD];           // [n][j]
__device__ __half g_q[BATCH*NHEAD*SEQ*HDIM];    // prescaled
__device__ __half g_k[BATCH*NHEAD*SEQ*HDIM];
__device__ __half g_vT[BATCH*NHEAD*HDIM*SEQ];   // [b,h,d,t]
__device__ __half g_attn[BATCH*NHEAD*SEQ*HDIM];

// ---------------------------------------------------------------------------
__device__ __forceinline__ uint32_t smem_u32(const void* p) {
    return (uint32_t)__cvta_generic_to_shared(p);
}
__device__ __forceinline__ void ldsm4(uint32_t* r, uint32_t a) {
    asm volatile("ldmatrix.sync.aligned.m8n8.x4.shared.b16 {%0,%1,%2,%3}, [%4];"
        : "=r"(r[0]), "=r"(r[1]), "=r"(r[2]), "=r"(r[3]) : "r"(a) : "memory");
}
__device__ __forceinline__ void mma16(float* c, const uint32_t* a, uint32_t b0, uint32_t b1) {
    asm volatile("mma.sync.aligned.m16n8k16.row.col.f32.f16.f16.f32 "
        "{%0,%1,%2,%3},{%4,%5,%6,%7},{%8,%9},{%0,%1,%2,%3};"
        : "+f"(c[0]), "+f"(c[1]), "+f"(c[2]), "+f"(c[3])
        : "r"(a[0]), "r"(a[1]), "r"(a[2]), "r"(a[3]), "r"(b0), "r"(b1));
}
__device__ __forceinline__ void cp16(uint32_t saddr, const void* g) {
    asm volatile("cp.async.cg.shared.global [%0], [%1], 16;" :: "r"(saddr), "l"(g));
}
#define CP_COMMIT() asm volatile("cp.async.commit_group;")
#define CP_WAIT1()  asm volatile("cp.async.wait_group 1;")
#define CP_WAIT0()  asm volatile("cp.async.wait_group 0;")

__device__ __forceinline__ uint32_t pack_h2(float a, float b) {
    __half2 h = __floats2half2_rn(a, b);
    return *reinterpret_cast<uint32_t*>(&h);
}
// SW128-style XOR swizzle for 128-byte rows of halves: byte offset of
// (row, colhalf) with 16B chunk index XORed by row&7. colhalf must be *8.
__device__ __forceinline__ uint32_t swz(int row, int colhalf) {
    uint32_t off = (uint32_t)(row * 128 + colhalf * 2);
    return off ^ (((uint32_t)row & 7u) << 4);
}

// ---------------------------------------------------------------------------
// conversions (unchanged)
// ---------------------------------------------------------------------------
__global__ __launch_bounds__(256) void cvt_kernel(
    const float4* __restrict__ in, uint2* __restrict__ out, int n4)
{
    int i = blockIdx.x * 256 + threadIdx.x;
    if (i < n4) {
        float4 v = in[i];
        out[i] = make_uint2(pack_h2(v.x, v.y), pack_h2(v.z, v.w));
    }
}

__global__ __launch_bounds__(256) void wt_kernel(
    const float* __restrict__ Wq, const float* __restrict__ Wk,
    const float* __restrict__ Wv)
{
    __shared__ float tile[32][33];
    const int zh = blockIdx.z;
    const int z = zh >> 4, h = zh & 15;
    const float* W = (z == 0 ? Wq : z == 1 ? Wk : Wv) + (size_t)h * EMBD * HDIM;
    const int c0 = blockIdx.x * 32, d0 = blockIdx.y * 32;
    const int t = threadIdx.x;
    const int r = t >> 3, c4 = (t & 7) * 4;

    float4 v = *(const float4*)&W[(size_t)(c0 + r) * HDIM + d0 + c4];
    tile[r][c4 + 0] = v.x; tile[r][c4 + 1] = v.y;
    tile[r][c4 + 2] = v.z; tile[r][c4 + 3] = v.w;
    __syncthreads();
    uint2 o = make_uint2(pack_h2(tile[c4 + 0][r], tile[c4 + 1][r]),
                         pack_h2(tile[c4 + 2][r], tile[c4 + 3][r]));
    *(uint2*)&g_wqkv[(size_t)(z * 1024 + h * 64 + d0 + r) * EMBD + c0 + c4] = o;
}

// ---------------------------------------------------------------------------
// QKV GEMM: C[8192,3072] = xt @ wqkv^T -> g_q/g_k/g_vT.
// Tile 128x128, BK=64, swizzled smem (16KB/tile stage), 2-stage cp.async.
// grid (64,24), 256 thr.
// ---------------------------------------------------------------------------
#define GSTG 16384                    // one 128x64-half tile, bytes
__global__ __launch_bounds__(256, 2) void qkv_kernel()
{
    extern __shared__ char smc[];
    const uint32_t sb = smem_u32(smc);
    const uint32_t Ab = sb;            // [2][16384]
    const uint32_t Bb = sb + 2 * GSTG;

    const int m0 = blockIdx.x * 128, n0 = blockIdx.y * 128;
    const int tid = threadIdx.x;
    const int lane = tid & 31, wid = tid >> 5;
    const int wm = wid & 3, wn = wid >> 2;
    const int lr = lane & 7, ls = lane >> 3;

    float acc[2][8][4];
#pragma unroll
    for (int mt = 0; mt < 2; mt++)
#pragma unroll
        for (int nt = 0; nt < 8; nt++)
#pragma unroll
            for (int c = 0; c < 4; c++) acc[mt][nt][c] = 0.f;

    const int a_row = wm * 32 + (lane & 15);
    const int a_k = (ls >> 1) * 8;
    const int b_row = wn * 64 + lr + ((ls >> 1) << 3);
    const int b_k = (ls & 1) * 8;

#define QKV_LOAD(st, k0)                                                      \
    {                                                                         \
        _Pragma("unroll")                                                     \
        for (int it = 0; it < 4; it++) {                                      \
            int idx = tid + it * 256;                                         \
            int r = idx >> 3, ch = (idx & 7) * 8;                             \
            cp16(Ab + (st) * GSTG + swz(r, ch),                               \
                 &g_xt[(size_t)(m0 + r) * EMBD + (k0) + ch]);                 \
            cp16(Bb + (st) * GSTG + swz(r, ch),                               \
                 &g_wqkv[(size_t)(n0 + r) * EMBD + (k0) + ch]);               \
        }                                                                     \
    }

    QKV_LOAD(0, 0); CP_COMMIT();

    for (int kt = 0; kt < 16; kt++) {
        const int cur = kt & 1;
        if (kt < 15) { QKV_LOAD(cur ^ 1, (kt + 1) * 64); CP_COMMIT(); CP_WAIT1(); }
        else CP_WAIT0();
        __syncthreads();
        const uint32_t A = Ab + cur * GSTG;
        const uint32_t B = Bb + cur * GSTG;
#pragma unroll
        for (int kk = 0; kk < 64; kk += 16) {
            uint32_t a[2][4];
            ldsm4(a[0], A + swz(a_row, kk + a_k));
            ldsm4(a[1], A + swz(a_row + 16, kk + a_k));
#pragma unroll
            for (int g = 0; g < 4; g++) {
                uint32_t b[4];
                ldsm4(b, B + swz(b_row + g * 16, kk + b_k));
                mma16(acc[0][2*g+0], a[0], b[0], b[1]);
                mma16(acc[0][2*g+1], a[0], b[2], b[3]);
                mma16(acc[1][2*g+0], a[1], b[0], b[1]);
                mma16(acc[1][2*g+1], a[1], b[2], b[3]);
            }
        }
        __syncthreads();
    }

    const int nb = n0 + wn * 64;
    const int zz = nb >> 10, h = (nb >> 6) & 15;
#pragma unroll
    for (int mt = 0; mt < 2; mt++) {
        int row = m0 + wm * 32 + mt * 16 + (lane >> 2);
        int b = row >> 11, t = row & 2047;
#pragma unroll
        for (int nt = 0; nt < 8; nt++) {
            int d = nt * 8 + 2 * (lane & 3);
            float c0f = acc[mt][nt][0], c1f = acc[mt][nt][1];
            float c2f = acc[mt][nt][2], c3f = acc[mt][nt][3];
            if (zz == 0) {
                __half* base = &g_q[(((size_t)(b * NHEAD + h)) * SEQ + t) * HDIM];
                *(uint32_t*)&base[d] = pack_h2(c0f * QK_SCALE_L2, c1f * QK_SCALE_L2);
                *(uint32_t*)&base[8 * HDIM + d] = pack_h2(c2f * QK_SCALE_L2, c3f * QK_SCALE_L2);
            } else if (zz == 1) {
                __half* base = &g_k[(((size_t)(b * NHEAD + h)) * SEQ + t) * HDIM];
                *(uint32_t*)&base[d] = pack_h2(c0f, c1f);
                *(uint32_t*)&base[8 * HDIM + d] = pack_h2(c2f, c3f);
            } else {
                __half* base = &g_vT[((size_t)(b * NHEAD + h)) * HDIM * SEQ];
                base[(size_t)(d    ) * SEQ + t    ] = __float2half_rn(c0f);
                base[(size_t)(d + 1) * SEQ + t    ] = __float2half_rn(c1f);
                base[(size_t)(d    ) * SEQ + t + 8] = __float2half_rn(c2f);
                base[(size_t)(d + 1) * SEQ + t + 8] = __float2half_rn(c3f);
            }
        }
    }
#undef QKV_LOAD
}

// ---------------------------------------------------------------------------
// Flash attention: Q 128, K/V 64, swizzled smem, P kept in registers (FA2).
// grid (16,64), 256 thr, smem 48KB -> 2 CTA/SM.
// ---------------------------------------------------------------------------
#define KSTG 8192                     // one 64x64-half tile, bytes
__global__ __launch_bounds__(256, 2) void attn_kernel()
{
    extern __shared__ char smc[];
    const uint32_t sb = smem_u32(smc);
    const uint32_t Qb = sb;            // 128x64 halves (16KB)
    const uint32_t Kb = sb + 16384;    // [2][8192]
    const uint32_t Vb = sb + 32768;    // [2][8192], rows=d cols=t

    const int qt = blockIdx.x, bh = blockIdx.y;
    const int m0 = qt * 128;
    const int tid = threadIdx.x;
    const int lane = tid & 31, wid = tid >> 5;
    const int lr = lane & 7, ls = lane >> 3;

    const __half* qp = g_q + (size_t)bh * SEQ * HDIM;
    const __half* kp = g_k + (size_t)bh * SEQ * HDIM;
    const __half* vp = g_vT + (size_t)bh * HDIM * SEQ;

#pragma unroll
    for (int it = 0; it < 4; it++) {
        int idx = tid + it * 256;
        int r = idx >> 3, ch = (idx & 7) * 8;
        cp16(Qb + swz(r, ch), &qp[(size_t)(m0 + r) * HDIM + ch]);
    }
#define KV_LOAD(st, n0_)                                                      \
    {                                                                         \
        _Pragma("unroll")                                                     \
        for (int it = 0; it < 2; it++) {                                      \
            int idx = tid + it * 256;                                         \
            int r = idx >> 3, ch = (idx & 7) * 8;                             \
            cp16(Kb + (st) * KSTG + swz(r, ch),                               \
                 &kp[(size_t)((n0_) + r) * HDIM + ch]);                       \
            cp16(Vb + (st) * KSTG + swz(r, ch),                               \
                 &vp[(size_t)r * SEQ + (n0_) + ch]);                          \
        }                                                                     \
    }
    KV_LOAD(0, 0); CP_COMMIT();

    float o[8][4];
#pragma unroll
    for (int nt = 0; nt < 8; nt++)
#pragma unroll
        for (int c = 0; c < 4; c++) o[nt][c] = 0.f;
    float mrow[2] = { -INFINITY, -INFINITY };
    float lrow[2] = { 0.f, 0.f };

    const int s_arow = wid * 16 + (lane & 15);
    const int s_ak = (ls >> 1) * 8;
    const int s_brow = lr + ((ls >> 1) << 3);
    const int s_bk = (ls & 1) * 8;

    const int jtmax = 2 * qt + 1;
    for (int jt = 0; jt <= jtmax; jt++) {
        const int cur = jt & 1;
        if (jt < jtmax) { KV_LOAD(cur ^ 1, (jt + 1) * 64); CP_COMMIT(); CP_WAIT1(); }
        else CP_WAIT0();
        __syncthreads();
        const uint32_t K = Kb + cur * KSTG;
        const uint32_t V = Vb + cur * KSTG;

        // S = Q K^T
        float s[8][4];
#pragma unroll
        for (int nt = 0; nt < 8; nt++)
#pragma unroll
            for (int c = 0; c < 4; c++) s[nt][c] = 0.f;
#pragma unroll
        for (int kk = 0; kk < 64; kk += 16) {
            uint32_t a[4];
            ldsm4(a, Qb + swz(s_arow, kk + s_ak));
#pragma unroll
            for (int g = 0; g < 4; g++) {
                uint32_t b[4];
                ldsm4(b, K + swz(g * 16 + s_brow, kk + s_bk));
                mma16(s[2*g+0], a, b[0], b[1]);
                mma16(s[2*g+1], a, b[2], b[3]);
            }
        }

        const int grow = m0 + wid * 16 + (lane >> 2);
        if (jt >= 2 * qt) {
            const int n0 = jt * 64;
#pragma unroll
            for (int nt = 0; nt < 8; nt++) {
                int col = n0 + nt * 8 + 2 * (lane & 3);
                if (col     > grow)     s[nt][0] = -INFINITY;
                if (col + 1 > grow)     s[nt][1] = -INFINITY;
                if (col     > grow + 8) s[nt][2] = -INFINITY;
                if (col + 1 > grow + 8) s[nt][3] = -INFINITY;
            }
        }

        // online softmax (log2 domain)
        float mx0 = -INFINITY, mx1 = -INFINITY;
#pragma unroll
        for (int nt = 0; nt < 8; nt++) {
            mx0 = fmaxf(mx0, fmaxf(s[nt][0], s[nt][1]));
            mx1 = fmaxf(mx1, fmaxf(s[nt][2], s[nt][3]));
        }
        mx0 = fmaxf(mx0, __shfl_xor_sync(0xffffffffu, mx0, 1));
        mx0 = fmaxf(mx0, __shfl_xor_sync(0xffffffffu, mx0, 2));
        mx1 = fmaxf(mx1, __shfl_xor_sync(0xffffffffu, mx1, 1));
        mx1 = fmaxf(mx1, __shfl_xor_sync(0xffffffffu, mx1, 2));
        float mn0 = fmaxf(mrow[0], mx0), mn1 = fmaxf(mrow[1], mx1);
        float al0 = exp2f(mrow[0] - mn0), al1 = exp2f(mrow[1] - mn1);
        float rs0 = 0.f, rs1 = 0.f;
#pragma unroll
        for (int nt = 0; nt < 8; nt++) {
            s[nt][0] = exp2f(s[nt][0] - mn0); rs0 += s[nt][0];
            s[nt][1] = exp2f(s[nt][1] - mn0); rs0 += s[nt][1];
            s[nt][2] = exp2f(s[nt][2] - mn1); rs1 += s[nt][2];
            s[nt][3] = exp2f(s[nt][3] - mn1); rs1 += s[nt][3];
        }
        rs0 += __shfl_xor_sync(0xffffffffu, rs0, 1);
        rs0 += __shfl_xor_sync(0xffffffffu, rs0, 2);
        rs1 += __shfl_xor_sync(0xffffffffu, rs1, 1);
        rs1 += __shfl_xor_sync(0xffffffffu, rs1, 2);
        lrow[0] = lrow[0] * al0 + rs0; mrow[0] = mn0;
        lrow[1] = lrow[1] * al1 + rs1; mrow[1] = mn1;
#pragma unroll
        for (int nt = 0; nt < 8; nt++) {
            o[nt][0] *= al0; o[nt][1] *= al0;
            o[nt][2] *= al1; o[nt][3] *= al1;
        }

        // O += P @ V with P straight from S fragments (FA2 register trick):
        // A-frag(k=16 grp j) = {h2(s[2j][0..1]), h2(s[2j][2..3]),
        //                       h2(s[2j+1][0..1]), h2(s[2j+1][2..3])}
#pragma unroll
        for (int j = 0; j < 4; j++) {
            uint32_t a[4];
            a[0] = pack_h2(s[2*j  ][0], s[2*j  ][1]);
            a[1] = pack_h2(s[2*j  ][2], s[2*j  ][3]);
            a[2] = pack_h2(s[2*j+1][0], s[2*j+1][1]);
            a[3] = pack_h2(s[2*j+1][2], s[2*j+1][3]);
            const int kk = j * 16;
#pragma unroll
            for (int g = 0; g < 4; g++) {
                uint32_t b[4];
                ldsm4(b, V + swz(g * 16 + s_brow, kk + s_bk));
                mma16(o[2*g+0], a, b[0], b[1]);
                mma16(o[2*g+1], a, b[2], b[3]);
            }
        }
        __syncthreads();
    }

    {
        float inv0 = 1.f / lrow[0], inv1 = 1.f / lrow[1];
        int row = m0 + wid * 16 + (lane >> 2);
        __half* op = g_attn + ((size_t)bh * SEQ + row) * HDIM;
#pragma unroll
        for (int nt = 0; nt < 8; nt++) {
            int col = nt * 8 + 2 * (lane & 3);
            *(uint32_t*)&op[col] = pack_h2(o[nt][0] * inv0, o[nt][1] * inv0);
            *(uint32_t*)&op[8 * HDIM + col] = pack_h2(o[nt][2] * inv1, o[nt][3] * inv1);
        }
    }
#undef KV_LOAD
}

// ---------------------------------------------------------------------------
// Output projection: out = attn @ wproj^T + bias. Tile 128x128, BK=64,
// swizzled, 2-stage. grid (64,8), 256 thr.
// ---------------------------------------------------------------------------
__global__ __launch_bounds__(256, 2) void proj_kernel(
    const float* __restrict__ bproj, float* __restrict__ out)
{
    extern __shared__ char smc[];
    const uint32_t sb = smem_u32(smc);
    const uint32_t Ab = sb;
    const uint32_t Bb = sb + 2 * GSTG;

    const int m0 = blockIdx.x * 128, n0 = blockIdx.y * 128;
    const int tid = threadIdx.x;
    const int lane = tid & 31, wid = tid >> 5;
    const int wm = wid & 3, wn = wid >> 2;
    const int lr = lane & 7, ls = lane >> 3;

    float acc[2][8][4];
#pragma unroll
    for (int mt = 0; mt < 2; mt++)
#pragma unroll
        for (int nt = 0; nt < 8; nt++)
#pragma unroll
            for (int c = 0; c < 4; c++) acc[mt][nt][c] = 0.f;

    const int a_row = wm * 32 + (lane & 15);
    const int a_k = (ls >> 1) * 8;
    const int b_row = wn * 64 + lr + ((ls >> 1) << 3);
    const int b_k = (ls & 1) * 8;

#define PROJ_LOAD(st, kt_)                                                    \
    {                                                                         \
        _Pragma("unroll")                                                     \
        for (int it = 0; it < 4; it++) {                                      \
            int idx = tid + it * 256;                                         \
            int r = idx >> 3, ch = (idx & 7) * 8;                             \
            int bt = m0 + r, b_ = bt >> 11, t_ = bt & 2047;                   \
            cp16(Ab + (st) * GSTG + swz(r, ch),                               \
                 &g_attn[(((size_t)(b_ * NHEAD + (kt_))) * SEQ + t_) * HDIM + ch]); \
            cp16(Bb + (st) * GSTG + swz(r, ch),                               \
                 &g_wproj[(size_t)(n0 + r) * EMBD + (kt_) * 64 + ch]);        \
        }                                                                     \
    }

    PROJ_LOAD(0, 0); CP_COMMIT();

    for (int kt = 0; kt < 16; kt++) {
        const int cur = kt & 1;
        if (kt < 15) { PROJ_LOAD(cur ^ 1, kt + 1); CP_COMMIT(); CP_WAIT1(); }
        else CP_WAIT0();
        __syncthreads();
        const uint32_t A = Ab + cur * GSTG;
        const uint32_t B = Bb + cur * GSTG;
#pragma unroll
        for (int kk = 0; kk < 64; kk += 16) {
            uint32_t a[2][4];
            ldsm4(a[0], A + swz(a_row, kk + a_k));
            ldsm4(a[1], A + swz(a_row + 16, kk + a_k));
#pragma unroll
            for (int g = 0; g < 4; g++) {
                uint32_t b[4];
                ldsm4(b, B + swz(b_row + g * 16, kk + b_k));
                mma16(acc[0][2*g+0], a[0], b[0], b[1]);
                mma16(acc[0][2*g+1], a[0], b[2], b[3]);
                mma16(acc[1][2*g+0], a[1], b[0], b[1]);
                mma16(acc[1][2*g+1], a[1], b[2], b[3]);
            }
        }
        __syncthreads();
    }

#pragma unroll
    for (int mt = 0; mt < 2; mt++) {
        int row = m0 + wm * 32 + mt * 16 + (lane >> 2);
        float* o0 = out + (size_t)row * EMBD;
        float* o1 = out + (size_t)(row + 8) * EMBD;
#pragma unroll
        for (int nt = 0; nt < 8; nt++) {
            int col = n0 + wn * 64 + nt * 8 + 2 * (lane & 3);
            float b0 = bproj[col], b1 = bproj[col + 1];
            *(float2*)&o0[col] = make_float2(acc[mt][nt][0] + b0, acc[mt][nt][1] + b1);
            *(float2*)&o1[col] = make_float2(acc[mt][nt][2] + b0, acc[mt][nt][3] + b1);
        }
    }
#undef PROJ_LOAD
}

// ---------------------------------------------------------------------------
extern "C" void kernel_launch(void* const* d_in, const int* in_sizes, int n_in,
                              void* d_out, int out_size)
{
    const float* x     = (const float*)d_in[0];
    const float* Wq    = (const float*)d_in[1];
    const float* Wk    = (const float*)d_in[2];
    const float* Wv    = (const float*)d_in[3];
    const float* Wproj = (const float*)d_in[4];
    const float* bproj = (const float*)d_in[5];
    float* out = (float*)d_out;

    __half* xt_p;     cudaGetSymbolAddress((void**)&xt_p, g_xt);
    __half* wproj_p;  cudaGetSymbolAddress((void**)&wproj_p, g_wproj);

    cvt_kernel<<<(MTOT * EMBD / 4 + 255) / 256, 256>>>(
        (const float4*)x, (uint2*)xt_p, MTOT * EMBD / 4);
    cvt_kernel<<<(EMBD * EMBD / 4 + 255) / 256, 256>>>(
        (const float4*)Wproj, (uint2*)wproj_p, EMBD * EMBD / 4);
    wt_kernel<<<dim3(EMBD / 32, HDIM / 32, 48), 256>>>(Wq, Wk, Wv);

    const int gemm_smem = 4 * GSTG;                        // 65536
    cudaFuncSetAttribute(qkv_kernel, cudaFuncAttributeMaxDynamicSharedMemorySize, gemm_smem);
    cudaFuncSetAttribute(proj_kernel, cudaFuncAttributeMaxDynamicSharedMemorySize, gemm_smem);

    qkv_kernel<<<dim3(MTOT / 128, NQKV / 128), 256, gemm_smem>>>();

    const int attn_smem = 16384 + 2 * KSTG + 2 * KSTG;     // 49152
    cudaFuncSetAttribute(attn_kernel, cudaFuncAttributeMaxDynamicSharedMemorySize, attn_smem);
    attn_kernel<<<dim3(SEQ / 128, BATCH * NHEAD), 256, attn_smem>>>();

    proj_kernel<<<dim3(MTOT / 128, EMBD / 128), 256, gemm_smem>>>(bproj, out);
}

// round 8
// speedup vs baseline: 8.3261x; 1.0220x over previous
#include <cuda_runtime.h>
#include <cuda_fp16.h>
#include <math.h>
#include <stdint.h>

#define BATCH 4
#define SEQ   2048
#define EMBD  1024
#define NHEAD 16
#define HDIM  64
#define MTOT  (BATCH*SEQ)            // 8192
#define NQKV  (3*NHEAD*HDIM)         // 3072
#define QK_SCALE_L2 (0.03125f * 1.44269504088896340736f)

// fp16 scratch
__device__ __half g_xt[MTOT*EMBD];
__device__ __half g_wqkv[NQKV*EMBD];            // [n][c], n = z*1024+h*64+d
__device__ __half g_wproj[EMBD*EMBD];           // [n][j]
__device__ __half g_q[BATCH*NHEAD*SEQ*HDIM];    // prescaled
__device__ __half g_k[BATCH*NHEAD*SEQ*HDIM];
__device__ __half g_vT[BATCH*NHEAD*HDIM*SEQ];   // [b,h,d,t]
__device__ __half g_attn[BATCH*NHEAD*SEQ*HDIM];

// ---------------------------------------------------------------------------
__device__ __forceinline__ uint32_t smem_u32(const void* p) {
    return (uint32_t)__cvta_generic_to_shared(p);
}
__device__ __forceinline__ void ldsm4(uint32_t* r, uint32_t a) {
    asm volatile("ldmatrix.sync.aligned.m8n8.x4.shared.b16 {%0,%1,%2,%3}, [%4];"
        : "=r"(r[0]), "=r"(r[1]), "=r"(r[2]), "=r"(r[3]) : "r"(a) : "memory");
}
__device__ __forceinline__ void mma16(float* c, const uint32_t* a, uint32_t b0, uint32_t b1) {
    asm volatile("mma.sync.aligned.m16n8k16.row.col.f32.f16.f16.f32 "
        "{%0,%1,%2,%3},{%4,%5,%6,%7},{%8,%9},{%0,%1,%2,%3};"
        : "+f"(c[0]), "+f"(c[1]), "+f"(c[2]), "+f"(c[3])
        : "r"(a[0]), "r"(a[1]), "r"(a[2]), "r"(a[3]), "r"(b0), "r"(b1));
}
__device__ __forceinline__ void cp16(uint32_t saddr, const void* g) {
    asm volatile("cp.async.cg.shared.global [%0], [%1], 16;" :: "r"(saddr), "l"(g));
}
#define CP_COMMIT() asm volatile("cp.async.commit_group;")
#define CP_WAIT1()  asm volatile("cp.async.wait_group 1;")
#define CP_WAIT0()  asm volatile("cp.async.wait_group 0;")

__device__ __forceinline__ uint32_t pack_h2(float a, float b) {
    __half2 h = __floats2half2_rn(a, b);
    return *reinterpret_cast<uint32_t*>(&h);
}
// XOR swizzle for 128-byte rows of halves (colhalf multiple of 8)
__device__ __forceinline__ uint32_t swz(int row, int colhalf) {
    uint32_t off = (uint32_t)(row * 128 + colhalf * 2);
    return off ^ (((uint32_t)row & 7u) << 4);
}

// ---------------------------------------------------------------------------
// conversions
// ---------------------------------------------------------------------------
__global__ __launch_bounds__(256) void cvt_kernel(
    const float4* __restrict__ in, uint2* __restrict__ out, int n4)
{
    int i = blockIdx.x * 256 + threadIdx.x;
    if (i < n4) {
        float4 v = in[i];
        out[i] = make_uint2(pack_h2(v.x, v.y), pack_h2(v.z, v.w));
    }
}

__global__ __launch_bounds__(256) void wt_kernel(
    const float* __restrict__ Wq, const float* __restrict__ Wk,
    const float* __restrict__ Wv)
{
    __shared__ float tile[32][33];
    const int zh = blockIdx.z;
    const int z = zh >> 4, h = zh & 15;
    const float* W = (z == 0 ? Wq : z == 1 ? Wk : Wv) + (size_t)h * EMBD * HDIM;
    const int c0 = blockIdx.x * 32, d0 = blockIdx.y * 32;
    const int t = threadIdx.x;
    const int r = t >> 3, c4 = (t & 7) * 4;

    float4 v = *(const float4*)&W[(size_t)(c0 + r) * HDIM + d0 + c4];
    tile[r][c4 + 0] = v.x; tile[r][c4 + 1] = v.y;
    tile[r][c4 + 2] = v.z; tile[r][c4 + 3] = v.w;
    __syncthreads();
    uint2 o = make_uint2(pack_h2(tile[c4 + 0][r], tile[c4 + 1][r]),
                         pack_h2(tile[c4 + 2][r], tile[c4 + 3][r]));
    *(uint2*)&g_wqkv[(size_t)(z * 1024 + h * 64 + d0 + r) * EMBD + c0 + c4] = o;
}

// ---------------------------------------------------------------------------
// QKV GEMM: C[8192,3072] = xt @ wqkv^T. Tile 128x128, BK=64, 3-stage,
// one sync per k-tile. grid (64,24), 256 thr, smem 96KB -> 2 CTA/SM.
// ---------------------------------------------------------------------------
#define GSTG 16384                    // one 128x64-half tile, bytes
__global__ __launch_bounds__(256, 2) void qkv_kernel()
{
    extern __shared__ char smc[];
    const uint32_t sb = smem_u32(smc);
    const uint32_t Ab = sb;            // [3][16384]
    const uint32_t Bb = sb + 3 * GSTG;

    const int m0 = blockIdx.x * 128, n0 = blockIdx.y * 128;
    const int tid = threadIdx.x;
    const int lane = tid & 31, wid = tid >> 5;
    const int wm = wid & 3, wn = wid >> 2;
    const int lr = lane & 7, ls = lane >> 3;

    float acc[2][8][4];
#pragma unroll
    for (int mt = 0; mt < 2; mt++)
#pragma unroll
        for (int nt = 0; nt < 8; nt++)
#pragma unroll
            for (int c = 0; c < 4; c++) acc[mt][nt][c] = 0.f;

    const int a_row = wm * 32 + (lane & 15);
    const int a_k = (ls >> 1) * 8;
    const int b_row = wn * 64 + lr + ((ls >> 1) << 3);
    const int b_k = (ls & 1) * 8;

#define QKV_LOAD(st, k0)                                                      \
    {                                                                         \
        _Pragma("unroll")                                                     \
        for (int it = 0; it < 4; it++) {                                      \
            int idx = tid + it * 256;                                         \
            int r = idx >> 3, ch = (idx & 7) * 8;                             \
            cp16(Ab + (st) * GSTG + swz(r, ch),                               \
                 &g_xt[(size_t)(m0 + r) * EMBD + (k0) + ch]);                 \
            cp16(Bb + (st) * GSTG + swz(r, ch),                               \
                 &g_wqkv[(size_t)(n0 + r) * EMBD + (k0) + ch]);               \
        }                                                                     \
    }

    QKV_LOAD(0, 0);  CP_COMMIT();
    QKV_LOAD(1, 64); CP_COMMIT();

    for (int kt = 0; kt < 16; kt++) {
        const int cur = kt % 3;
        if (kt >= 14) CP_WAIT0(); else CP_WAIT1();
        __syncthreads();
        const uint32_t A = Ab + cur * GSTG;
        const uint32_t B = Bb + cur * GSTG;
#pragma unroll
        for (int kk = 0; kk < 64; kk += 16) {
            uint32_t a[2][4];
            ldsm4(a[0], A + swz(a_row, kk + a_k));
            ldsm4(a[1], A + swz(a_row + 16, kk + a_k));
#pragma unroll
            for (int g = 0; g < 4; g++) {
                uint32_t b[4];
                ldsm4(b, B + swz(b_row + g * 16, kk + b_k));
                mma16(acc[0][2*g+0], a[0], b[0], b[1]);
                mma16(acc[0][2*g+1], a[0], b[2], b[3]);
                mma16(acc[1][2*g+0], a[1], b[0], b[1]);
                mma16(acc[1][2*g+1], a[1], b[2], b[3]);
            }
        }
        if (kt < 14) { QKV_LOAD((kt + 2) % 3, (kt + 2) * 64); CP_COMMIT(); }
    }

    const int nb = n0 + wn * 64;
    const int zz = nb >> 10, h = (nb >> 6) & 15;
#pragma unroll
    for (int mt = 0; mt < 2; mt++) {
        int row = m0 + wm * 32 + mt * 16 + (lane >> 2);
        int b = row >> 11, t = row & 2047;
#pragma unroll
        for (int nt = 0; nt < 8; nt++) {
            int d = nt * 8 + 2 * (lane & 3);
            float c0f = acc[mt][nt][0], c1f = acc[mt][nt][1];
            float c2f = acc[mt][nt][2], c3f = acc[mt][nt][3];
            if (zz == 0) {
                __half* base = &g_q[(((size_t)(b * NHEAD + h)) * SEQ + t) * HDIM];
                *(uint32_t*)&base[d] = pack_h2(c0f * QK_SCALE_L2, c1f * QK_SCALE_L2);
                *(uint32_t*)&base[8 * HDIM + d] = pack_h2(c2f * QK_SCALE_L2, c3f * QK_SCALE_L2);
            } else if (zz == 1) {
                __half* base = &g_k[(((size_t)(b * NHEAD + h)) * SEQ + t) * HDIM];
                *(uint32_t*)&base[d] = pack_h2(c0f, c1f);
                *(uint32_t*)&base[8 * HDIM + d] = pack_h2(c2f, c3f);
            } else {
                __half* base = &g_vT[((size_t)(b * NHEAD + h)) * HDIM * SEQ];
                base[(size_t)(d    ) * SEQ + t    ] = __float2half_rn(c0f);
                base[(size_t)(d + 1) * SEQ + t    ] = __float2half_rn(c1f);
                base[(size_t)(d    ) * SEQ + t + 8] = __float2half_rn(c2f);
                base[(size_t)(d + 1) * SEQ + t + 8] = __float2half_rn(c3f);
            }
        }
    }
#undef QKV_LOAD
}

// ---------------------------------------------------------------------------
// Flash attention: Q 128, K/V 64, swizzled, register-P, 3-stage KV pipeline,
// one sync per kv-tile, longest-CTA-first launch order.
// grid (16,64), 256 thr, smem 64KB -> 2 CTA/SM.
// ---------------------------------------------------------------------------
#define KSTG 8192                     // one 64x64-half tile, bytes
__global__ __launch_bounds__(256, 2) void attn_kernel()
{
    extern __shared__ char smc[];
    const uint32_t sb = smem_u32(smc);
    const uint32_t Qb = sb;            // 128x64 halves (16KB)
    const uint32_t Kb = sb + 16384;    // [3][8192]
    const uint32_t Vb = sb + 16384 + 3 * KSTG;   // [3][8192], rows=d cols=t

    const int qt = (int)gridDim.x - 1 - (int)blockIdx.x;   // longest first
    const int bh = blockIdx.y;
    const int m0 = qt * 128;
    const int tid = threadIdx.x;
    const int lane = tid & 31, wid = tid >> 5;
    const int lr = lane & 7, ls = lane >> 3;

    const __half* qp = g_q + (size_t)bh * SEQ * HDIM;
    const __half* kp = g_k + (size_t)bh * SEQ * HDIM;
    const __half* vp = g_vT + (size_t)bh * HDIM * SEQ;

    // Q joins cp.async group 0
#pragma unroll
    for (int it = 0; it < 4; it++) {
        int idx = tid + it * 256;
        int r = idx >> 3, ch = (idx & 7) * 8;
        cp16(Qb + swz(r, ch), &qp[(size_t)(m0 + r) * HDIM + ch]);
    }
#define KV_LOAD(st, n0_)                                                      \
    {                                                                         \
        _Pragma("unroll")                                                     \
        for (int it = 0; it < 2; it++) {                                      \
            int idx = tid + it * 256;                                         \
            int r = idx >> 3, ch = (idx & 7) * 8;                             \
            cp16(Kb + (st) * KSTG + swz(r, ch),                               \
                 &kp[(size_t)((n0_) + r) * HDIM + ch]);                       \
            cp16(Vb + (st) * KSTG + swz(r, ch),                               \
                 &vp[(size_t)r * SEQ + (n0_) + ch]);                          \
        }                                                                     \
    }
    const int jtmax = 2 * qt + 1;
    KV_LOAD(0, 0); CP_COMMIT();
    KV_LOAD(1, 64); CP_COMMIT();      // jtmax >= 1 always

    float o[8][4];
#pragma unroll
    for (int nt = 0; nt < 8; nt++)
#pragma unroll
        for (int c = 0; c < 4; c++) o[nt][c] = 0.f;
    float mrow[2] = { -INFINITY, -INFINITY };
    float lrow[2] = { 0.f, 0.f };

    const int s_arow = wid * 16 + (lane & 15);
    const int s_ak = (ls >> 1) * 8;
    const int s_brow = lr + ((ls >> 1) << 3);
    const int s_bk = (ls & 1) * 8;

    for (int jt = 0; jt <= jtmax; jt++) {
        const int cur = jt % 3;
        if (jt >= jtmax - 1) CP_WAIT0(); else CP_WAIT1();
        __syncthreads();
        const uint32_t K = Kb + cur * KSTG;
        const uint32_t V = Vb + cur * KSTG;

        // S = Q K^T
        float s[8][4];
#pragma unroll
        for (int nt = 0; nt < 8; nt++)
#pragma unroll
            for (int c = 0; c < 4; c++) s[nt][c] = 0.f;
#pragma unroll
        for (int kk = 0; kk < 64; kk += 16) {
            uint32_t a[4];
            ldsm4(a, Qb + swz(s_arow, kk + s_ak));
#pragma unroll
            for (int g = 0; g < 4; g++) {
                uint32_t b[4];
                ldsm4(b, K + swz(g * 16 + s_brow, kk + s_bk));
                mma16(s[2*g+0], a, b[0], b[1]);
                mma16(s[2*g+1], a, b[2], b[3]);
            }
        }

        const int grow = m0 + wid * 16 + (lane >> 2);
        if (jt >= 2 * qt) {
            const int n0 = jt * 64;
#pragma unroll
            for (int nt = 0; nt < 8; nt++) {
                int col = n0 + nt * 8 + 2 * (lane & 3);
                if (col     > grow)     s[nt][0] = -INFINITY;
                if (col + 1 > grow)     s[nt][1] = -INFINITY;
                if (col     > grow + 8) s[nt][2] = -INFINITY;
                if (col + 1 > grow + 8) s[nt][3] = -INFINITY;
            }
        }

        // online softmax (log2 domain)
        float mx0 = -INFINITY, mx1 = -INFINITY;
#pragma unroll
        for (int nt = 0; nt < 8; nt++) {
            mx0 = fmaxf(mx0, fmaxf(s[nt][0], s[nt][1]));
            mx1 = fmaxf(mx1, fmaxf(s[nt][2], s[nt][3]));
        }
        mx0 = fmaxf(mx0, __shfl_xor_sync(0xffffffffu, mx0, 1));
        mx0 = fmaxf(mx0, __shfl_xor_sync(0xffffffffu, mx0, 2));
        mx1 = fmaxf(mx1, __shfl_xor_sync(0xffffffffu, mx1, 1));
        mx1 = fmaxf(mx1, __shfl_xor_sync(0xffffffffu, mx1, 2));
        float mn0 = fmaxf(mrow[0], mx0), mn1 = fmaxf(mrow[1], mx1);
        float al0 = exp2f(mrow[0] - mn0), al1 = exp2f(mrow[1] - mn1);
        float rs0 = 0.f, rs1 = 0.f;
#pragma unroll
        for (int nt = 0; nt < 8; nt++) {
            s[nt][0] = exp2f(s[nt][0] - mn0); rs0 += s[nt][0];
            s[nt][1] = exp2f(s[nt][1] - mn0); rs0 += s[nt][1];
            s[nt][2] = exp2f(s[nt][2] - mn1); rs1 += s[nt][2];
            s[nt][3] = exp2f(s[nt][3] - mn1); rs1 += s[nt][3];
        }
        rs0 += __shfl_xor_sync(0xffffffffu, rs0, 1);
        rs0 += __shfl_xor_sync(0xffffffffu, rs0, 2);
        rs1 += __shfl_xor_sync(0xffffffffu, rs1, 1);
        rs1 += __shfl_xor_sync(0xffffffffu, rs1, 2);
        lrow[0] = lrow[0] * al0 + rs0; mrow[0] = mn0;
        lrow[1] = lrow[1] * al1 + rs1; mrow[1] = mn1;
#pragma unroll
        for (int nt = 0; nt < 8; nt++) {
            o[nt][0] *= al0; o[nt][1] *= al0;
            o[nt][2] *= al1; o[nt][3] *= al1;
        }

        // O += P @ V, P from S fragments (FA2 register trick)
#pragma unroll
        for (int j = 0; j < 4; j++) {
            uint32_t a[4];
            a[0] = pack_h2(s[2*j  ][0], s[2*j  ][1]);
            a[1] = pack_h2(s[2*j  ][2], s[2*j  ][3]);
            a[2] = pack_h2(s[2*j+1][0], s[2*j+1][1]);
            a[3] = pack_h2(s[2*j+1][2], s[2*j+1][3]);
            const int kk = j * 16;
#pragma unroll
            for (int g = 0; g < 4; g++) {
                uint32_t b[4];
                ldsm4(b, V + swz(g * 16 + s_brow, kk + s_bk));
                mma16(o[2*g+0], a, b[0], b[1]);
                mma16(o[2*g+1], a, b[2], b[3]);
            }
        }

        if (jt + 2 <= jtmax) { KV_LOAD((jt + 2) % 3, (jt + 2) * 64); CP_COMMIT(); }
    }

    {
        float inv0 = 1.f / lrow[0], inv1 = 1.f / lrow[1];
        int row = m0 + wid * 16 + (lane >> 2);
        __half* op = g_attn + ((size_t)bh * SEQ + row) * HDIM;
#pragma unroll
        for (int nt = 0; nt < 8; nt++) {
            int col = nt * 8 + 2 * (lane & 3);
            *(uint32_t*)&op[col] = pack_h2(o[nt][0] * inv0, o[nt][1] * inv0);
            *(uint32_t*)&op[8 * HDIM + col] = pack_h2(o[nt][2] * inv1, o[nt][3] * inv1);
        }
    }
#undef KV_LOAD
}

// ---------------------------------------------------------------------------
// Output projection: out = attn @ wproj^T + bias. Tile 128x128, BK=64,
// 3-stage, one sync per k-tile. grid (64,8), 256 thr.
// ---------------------------------------------------------------------------
__global__ __launch_bounds__(256, 2) void proj_kernel(
    const float* __restrict__ bproj, float* __restrict__ out)
{
    extern __shared__ char smc[];
    const uint32_t sb = smem_u32(smc);
    const uint32_t Ab = sb;
    const uint32_t Bb = sb + 3 * GSTG;

    const int m0 = blockIdx.x * 128, n0 = blockIdx.y * 128;
    const int tid = threadIdx.x;
    const int lane = tid & 31, wid = tid >> 5;
    const int wm = wid & 3, wn = wid >> 2;
    const int lr = lane & 7, ls = lane >> 3;

    float acc[2][8][4];
#pragma unroll
    for (int mt = 0; mt < 2; mt++)
#pragma unroll
        for (int nt = 0; nt < 8; nt++)
#pragma unroll
            for (int c = 0; c < 4; c++) acc[mt][nt][c] = 0.f;

    const int a_row = wm * 32 + (lane & 15);
    const int a_k = (ls >> 1) * 8;
    const int b_row = wn * 64 + lr + ((ls >> 1) << 3);
    const int b_k = (ls & 1) * 8;

#define PROJ_LOAD(st, kt_)                                                    \
    {                                                                         \
        _Pragma("unroll")                                                     \
        for (int it = 0; it < 4; it++) {                                      \
            int idx = tid + it * 256;                                         \
            int r = idx >> 3, ch = (idx & 7) * 8;                             \
            int bt = m0 + r, b_ = bt >> 11, t_ = bt & 2047;                   \
            cp16(Ab + (st) * GSTG + swz(r, ch),                               \
                 &g_attn[(((size_t)(b_ * NHEAD + (kt_))) * SEQ + t_) * HDIM + ch]); \
            cp16(Bb + (st) * GSTG + swz(r, ch),                               \
                 &g_wproj[(size_t)(n0 + r) * EMBD + (kt_) * 64 + ch]);        \
        }                                                                     \
    }

    PROJ_LOAD(0, 0); CP_COMMIT();
    PROJ_LOAD(1, 1); CP_COMMIT();

    for (int kt = 0; kt < 16; kt++) {
        const int cur = kt % 3;
        if (kt >= 14) CP_WAIT0(); else CP_WAIT1();
        __syncthreads();
        const uint32_t A = Ab + cur * GSTG;
        const uint32_t B = Bb + cur * GSTG;
#pragma unroll
        for (int kk = 0; kk < 64; kk += 16) {
            uint32_t a[2][4];
            ldsm4(a[0], A + swz(a_row, kk + a_k));
            ldsm4(a[1], A + swz(a_row + 16, kk + a_k));
#pragma unroll
            for (int g = 0; g < 4; g++) {
                uint32_t b[4];
                ldsm4(b, B + swz(b_row + g * 16, kk + b_k));
                mma16(acc[0][2*g+0], a[0], b[0], b[1]);
                mma16(acc[0][2*g+1], a[0], b[2], b[3]);
                mma16(acc[1][2*g+0], a[1], b[0], b[1]);
                mma16(acc[1][2*g+1], a[1], b[2], b[3]);
            }
        }
        if (kt < 14) { PROJ_LOAD((kt + 2) % 3, kt + 2); CP_COMMIT(); }
    }

#pragma unroll
    for (int mt = 0; mt < 2; mt++) {
        int row = m0 + wm * 32 + mt * 16 + (lane >> 2);
        float* o0 = out + (size_t)row * EMBD;
        float* o1 = out + (size_t)(row + 8) * EMBD;
#pragma unroll
        for (int nt = 0; nt < 8; nt++) {
            int col = n0 + wn * 64 + nt * 8 + 2 * (lane & 3);
            float b0 = bproj[col], b1 = bproj[col + 1];
            *(float2*)&o0[col] = make_float2(acc[mt][nt][0] + b0, acc[mt][nt][1] + b1);
            *(float2*)&o1[col] = make_float2(acc[mt][nt][2] + b0, acc[mt][nt][3] + b1);
        }
    }
#undef PROJ_LOAD
}

// ---------------------------------------------------------------------------
extern "C" void kernel_launch(void* const* d_in, const int* in_sizes, int n_in,
                              void* d_out, int out_size)
{
    const float* x     = (const float*)d_in[0];
    const float* Wq    = (const float*)d_in[1];
    const float* Wk    = (const float*)d_in[2];
    const float* Wv    = (const float*)d_in[3];
    const float* Wproj = (const float*)d_in[4];
    const float* bproj = (const float*)d_in[5];
    float* out = (float*)d_out;

    __half* xt_p;     cudaGetSymbolAddress((void**)&xt_p, g_xt);
    __half* wproj_p;  cudaGetSymbolAddress((void**)&wproj_p, g_wproj);

    cvt_kernel<<<(MTOT * EMBD / 4 + 255) / 256, 256>>>(
        (const float4*)x, (uint2*)xt_p, MTOT * EMBD / 4);
    cvt_kernel<<<(EMBD * EMBD / 4 + 255) / 256, 256>>>(
        (const float4*)Wproj, (uint2*)wproj_p, EMBD * EMBD / 4);
    wt_kernel<<<dim3(EMBD / 32, HDIM / 32, 48), 256>>>(Wq, Wk, Wv);

    const int gemm_smem = 6 * GSTG;                        // 98304
    cudaFuncSetAttribute(qkv_kernel, cudaFuncAttributeMaxDynamicSharedMemorySize, gemm_smem);
    cudaFuncSetAttribute(proj_kernel, cudaFuncAttributeMaxDynamicSharedMemorySize, gemm_smem);

    qkv_kernel<<<dim3(MTOT / 128, NQKV / 128), 256, gemm_smem>>>();

    const int attn_smem = 16384 + 6 * KSTG;                // 65536
    cudaFuncSetAttribute(attn_kernel, cudaFuncAttributeMaxDynamicSharedMemorySize, attn_smem);
    attn_kernel<<<dim3(SEQ / 128, BATCH * NHEAD), 256, attn_smem>>>();

    proj_kernel<<<dim3(MTOT / 128, EMBD / 128), 256, gemm_smem>>>(bproj, out);
}

// round 10
// speedup vs baseline: 8.4663x; 1.0168x over previous
#include <cuda_runtime.h>
#include <cuda_fp16.h>
#include <math.h>
#include <stdint.h>

#define BATCH 4
#define SEQ   2048
#define EMBD  1024
#define NHEAD 16
#define HDIM  64
#define MTOT  (BATCH*SEQ)            // 8192
#define NQKV  (3*NHEAD*HDIM)         // 3072
#define QK_SCALE_L2 (0.03125f * 1.44269504088896340736f)

// fp16 scratch
__device__ __half g_xt[MTOT*EMBD];
__device__ __half g_wqkv[NQKV*EMBD];            // [n][c], n = z*1024+h*64+d
__device__ __half g_wproj[EMBD*EMBD];           // [n][j]
__device__ __half g_q[BATCH*NHEAD*SEQ*HDIM];    // prescaled
__device__ __half g_k[BATCH*NHEAD*SEQ*HDIM];
__device__ __half g_v[BATCH*NHEAD*SEQ*HDIM];    // [b,h,t,d]
__device__ __half g_attn[BATCH*NHEAD*SEQ*HDIM];

// ---------------------------------------------------------------------------
__device__ __forceinline__ uint32_t smem_u32(const void* p) {
    return (uint32_t)__cvta_generic_to_shared(p);
}
__device__ __forceinline__ void ldsm4(uint32_t* r, uint32_t a) {
    asm volatile("ldmatrix.sync.aligned.m8n8.x4.shared.b16 {%0,%1,%2,%3}, [%4];"
        : "=r"(r[0]), "=r"(r[1]), "=r"(r[2]), "=r"(r[3]) : "r"(a) : "memory");
}
__device__ __forceinline__ void ldsm4t(uint32_t* r, uint32_t a) {
    asm volatile("ldmatrix.sync.aligned.m8n8.x4.trans.shared.b16 {%0,%1,%2,%3}, [%4];"
        : "=r"(r[0]), "=r"(r[1]), "=r"(r[2]), "=r"(r[3]) : "r"(a) : "memory");
}
__device__ __forceinline__ void mma16(float* c, const uint32_t* a, uint32_t b0, uint32_t b1) {
    asm volatile("mma.sync.aligned.m16n8k16.row.col.f32.f16.f16.f32 "
        "{%0,%1,%2,%3},{%4,%5,%6,%7},{%8,%9},{%0,%1,%2,%3};"
        : "+f"(c[0]), "+f"(c[1]), "+f"(c[2]), "+f"(c[3])
        : "r"(a[0]), "r"(a[1]), "r"(a[2]), "r"(a[3]), "r"(b0), "r"(b1));
}
__device__ __forceinline__ void cp16(uint32_t saddr, const void* g) {
    asm volatile("cp.async.cg.shared.global [%0], [%1], 16;" :: "r"(saddr), "l"(g));
}
#define CP_COMMIT() asm volatile("cp.async.commit_group;")
#define CP_WAIT1()  asm volatile("cp.async.wait_group 1;")
#define CP_WAIT0()  asm volatile("cp.async.wait_group 0;")

__device__ __forceinline__ uint32_t pack_h2(float a, float b) {
    __half2 h = __floats2half2_rn(a, b);
    return *reinterpret_cast<uint32_t*>(&h);
}
__device__ __forceinline__ uint32_t ex2h2(uint32_t x) {
    uint32_t d; asm("ex2.approx.f16x2 %0, %1;" : "=r"(d) : "r"(x)); return d;
}
// XOR swizzle for 128-byte rows of halves (colhalf multiple of 8)
__device__ __forceinline__ uint32_t swz(int row, int colhalf) {
    uint32_t off = (uint32_t)(row * 128 + colhalf * 2);
    return off ^ (((uint32_t)row & 7u) << 4);
}

// ---------------------------------------------------------------------------
// conversions
// ---------------------------------------------------------------------------
__global__ __launch_bounds__(256) void cvt_kernel(
    const float4* __restrict__ in, uint2* __restrict__ out, int n4)
{
    int i = blockIdx.x * 256 + threadIdx.x;
    if (i < n4) {
        float4 v = in[i];
        out[i] = make_uint2(pack_h2(v.x, v.y), pack_h2(v.z, v.w));
    }
}

__global__ __launch_bounds__(256) void wt_kernel(
    const float* __restrict__ Wq, const float* __restrict__ Wk,
    const float* __restrict__ Wv)
{
    __shared__ float tile[32][33];
    const int zh = blockIdx.z;
    const int z = zh >> 4, h = zh & 15;
    const float* W = (z == 0 ? Wq : z == 1 ? Wk : Wv) + (size_t)h * EMBD * HDIM;
    const int c0 = blockIdx.x * 32, d0 = blockIdx.y * 32;
    const int t = threadIdx.x;
    const int r = t >> 3, c4 = (t & 7) * 4;

    float4 v = *(const float4*)&W[(size_t)(c0 + r) * HDIM + d0 + c4];
    tile[r][c4 + 0] = v.x; tile[r][c4 + 1] = v.y;
    tile[r][c4 + 2] = v.z; tile[r][c4 + 3] = v.w;
    __syncthreads();
    uint2 o = make_uint2(pack_h2(tile[c4 + 0][r], tile[c4 + 1][r]),
                         pack_h2(tile[c4 + 2][r], tile[c4 + 3][r]));
    *(uint2*)&g_wqkv[(size_t)(z * 1024 + h * 64 + d0 + r) * EMBD + c0 + c4] = o;
}

// ---------------------------------------------------------------------------
// QKV GEMM: C[8192,3072] = xt @ wqkv^T. Tile 128x128, BK=64, 3-stage,
// one sync per k-tile. grid (64,24), 256 thr.
// ---------------------------------------------------------------------------
#define GSTG 16384                    // one 128x64-half tile, bytes
__global__ __launch_bounds__(256, 2) void qkv_kernel()
{
    extern __shared__ char smc[];
    const uint32_t sb = smem_u32(smc);
    const uint32_t Ab = sb;            // [3][16384]
    const uint32_t Bb = sb + 3 * GSTG;

    const int m0 = blockIdx.x * 128, n0 = blockIdx.y * 128;
    const int tid = threadIdx.x;
    const int lane = tid & 31, wid = tid >> 5;
    const int wm = wid & 3, wn = wid >> 2;
    const int lr = lane & 7, ls = lane >> 3;

    float acc[2][8][4];
#pragma unroll
    for (int mt = 0; mt < 2; mt++)
#pragma unroll
        for (int nt = 0; nt < 8; nt++)
#pragma unroll
            for (int c = 0; c < 4; c++) acc[mt][nt][c] = 0.f;

    const int a_row = wm * 32 + (lane & 15);
    const int a_k = (ls >> 1) * 8;
    const int b_row = wn * 64 + lr + ((ls >> 1) << 3);
    const int b_k = (ls & 1) * 8;

#define QKV_LOAD(st, k0)                                                      \
    {                                                                         \
        _Pragma("unroll")                                                     \
        for (int it = 0; it < 4; it++) {                                      \
            int idx = tid + it * 256;                                         \
            int r = idx >> 3, ch = (idx & 7) * 8;                             \
            cp16(Ab + (st) * GSTG + swz(r, ch),                               \
                 &g_xt[(size_t)(m0 + r) * EMBD + (k0) + ch]);                 \
            cp16(Bb + (st) * GSTG + swz(r, ch),                               \
                 &g_wqkv[(size_t)(n0 + r) * EMBD + (k0) + ch]);               \
        }                                                                     \
    }

    QKV_LOAD(0, 0);  CP_COMMIT();
    QKV_LOAD(1, 64); CP_COMMIT();

    for (int kt = 0; kt < 16; kt++) {
        const int cur = kt % 3;
        if (kt >= 14) CP_WAIT0(); else CP_WAIT1();
        __syncthreads();
        const uint32_t A = Ab + cur * GSTG;
        const uint32_t B = Bb + cur * GSTG;
#pragma unroll
        for (int kk = 0; kk < 64; kk += 16) {
            uint32_t a[2][4];
            ldsm4(a[0], A + swz(a_row, kk + a_k));
            ldsm4(a[1], A + swz(a_row + 16, kk + a_k));
#pragma unroll
            for (int g = 0; g < 4; g++) {
                uint32_t b[4];
                ldsm4(b, B + swz(b_row + g * 16, kk + b_k));
                mma16(acc[0][2*g+0], a[0], b[0], b[1]);
                mma16(acc[0][2*g+1], a[0], b[2], b[3]);
                mma16(acc[1][2*g+0], a[1], b[0], b[1]);
                mma16(acc[1][2*g+1], a[1], b[2], b[3]);
            }
        }
        if (kt < 14) { QKV_LOAD((kt + 2) % 3, (kt + 2) * 64); CP_COMMIT(); }
    }

    const int nb = n0 + wn * 64;
    const int zz = nb >> 10, h = (nb >> 6) & 15;
#pragma unroll
    for (int mt = 0; mt < 2; mt++) {
        int row = m0 + wm * 32 + mt * 16 + (lane >> 2);
        int b = row >> 11, t = row & 2047;
        __half* base = (zz == 0 ? g_q : zz == 1 ? g_k : g_v);
        base += (((size_t)(b * NHEAD + h)) * SEQ + t) * HDIM;
        const float sc = (zz == 0) ? QK_SCALE_L2 : 1.f;
#pragma unroll
        for (int nt = 0; nt < 8; nt++) {
            int d = nt * 8 + 2 * (lane & 3);
            *(uint32_t*)&base[d] = pack_h2(acc[mt][nt][0] * sc, acc[mt][nt][1] * sc);
            *(uint32_t*)&base[8 * HDIM + d] = pack_h2(acc[mt][nt][2] * sc, acc[mt][nt][3] * sc);
        }
    }
#undef QKV_LOAD
}

// ---------------------------------------------------------------------------
// Flash attention: Q 128, K/V 64 (both [t][d]), register-P via ex2.f16x2,
// l via ones-column mma (broadcast at epilogue), V via ldmatrix.trans,
// 3-stage KV pipeline. grid (16,64), 256 thr, smem 64KB -> 2 CTA/SM.
// ---------------------------------------------------------------------------
#define KSTG 8192                     // one 64x64-half tile, bytes
__global__ __launch_bounds__(256, 2) void attn_kernel()
{
    extern __shared__ char smc[];
    const uint32_t sb = smem_u32(smc);
    const uint32_t Qb = sb;            // 128x64 halves (16KB)
    const uint32_t Kb = sb + 16384;    // [3][8192]
    const uint32_t Vb = sb + 16384 + 3 * KSTG;   // [3][8192], rows=t cols=d

    const int qt = (int)gridDim.x - 1 - (int)blockIdx.x;   // longest first
    const int bh = blockIdx.y;
    const int m0 = qt * 128;
    const int tid = threadIdx.x;
    const int lane = tid & 31, wid = tid >> 5;
    const int lr = lane & 7, ls = lane >> 3;

    const __half* qp = g_q + (size_t)bh * SEQ * HDIM;
    const __half* kp = g_k + (size_t)bh * SEQ * HDIM;
    const __half* vp = g_v + (size_t)bh * SEQ * HDIM;

#pragma unroll
    for (int it = 0; it < 4; it++) {
        int idx = tid + it * 256;
        int r = idx >> 3, ch = (idx & 7) * 8;
        cp16(Qb + swz(r, ch), &qp[(size_t)(m0 + r) * HDIM + ch]);
    }
#define KV_LOAD(st, n0_)                                                      \
    {                                                                         \
        _Pragma("unroll")                                                     \
        for (int it = 0; it < 2; it++) {                                      \
            int idx = tid + it * 256;                                         \
            int r = idx >> 3, ch = (idx & 7) * 8;                             \
            cp16(Kb + (st) * KSTG + swz(r, ch),                               \
                 &kp[(size_t)((n0_) + r) * HDIM + ch]);                       \
            cp16(Vb + (st) * KSTG + swz(r, ch),                               \
                 &vp[(size_t)((n0_) + r) * HDIM + ch]);                       \
        }                                                                     \
    }
    const int jtmax = 2 * qt + 1;
    KV_LOAD(0, 0); CP_COMMIT();
    KV_LOAD(1, 64); CP_COMMIT();      // jtmax >= 1 always

    float o[8][4];
#pragma unroll
    for (int nt = 0; nt < 8; nt++)
#pragma unroll
        for (int c = 0; c < 4; c++) o[nt][c] = 0.f;
    float lacc[4] = { 0.f, 0.f, 0.f, 0.f };
    float mrow[2] = { -INFINITY, -INFINITY };

    const int s_arow = wid * 16 + (lane & 15);
    const int s_ak = (ls >> 1) * 8;
    const int s_brow = lr + ((ls >> 1) << 3);            // K (non-trans)
    const int s_bk = (ls & 1) * 8;
    const int v_row = lr + ((ls & 1) << 3);              // V (trans)
    const int v_col = (ls >> 1) << 3;
    const uint32_t onesb = ((lane >> 2) == 0) ? 0x3C003C00u : 0u;

    for (int jt = 0; jt <= jtmax; jt++) {
        const int cur = jt % 3;
        if (jt >= jtmax - 1) CP_WAIT0(); else CP_WAIT1();
        __syncthreads();
        const uint32_t K = Kb + cur * KSTG;
        const uint32_t V = Vb + cur * KSTG;

        // S = Q K^T
        float s[8][4];
#pragma unroll
        for (int nt = 0; nt < 8; nt++)
#pragma unroll
            for (int c = 0; c < 4; c++) s[nt][c] = 0.f;
#pragma unroll
        for (int kk = 0; kk < 64; kk += 16) {
            uint32_t a[4];
            ldsm4(a, Qb + swz(s_arow, kk + s_ak));
#pragma unroll
            for (int g = 0; g < 4; g++) {
                uint32_t b[4];
                ldsm4(b, K + swz(g * 16 + s_brow, kk + s_bk));
                mma16(s[2*g+0], a, b[0], b[1]);
                mma16(s[2*g+1], a, b[2], b[3]);
            }
        }

        const int grow = m0 + wid * 16 + (lane >> 2);
        if (jt >= 2 * qt) {
            const int n0 = jt * 64;
#pragma unroll
            for (int nt = 0; nt < 8; nt++) {
                int col = n0 + nt * 8 + 2 * (lane & 3);
                if (col     > grow)     s[nt][0] = -INFINITY;
                if (col + 1 > grow)     s[nt][1] = -INFINITY;
                if (col     > grow + 8) s[nt][2] = -INFINITY;
                if (col + 1 > grow + 8) s[nt][3] = -INFINITY;
            }
        }

        // row max (log2 domain)
        float mx0 = -INFINITY, mx1 = -INFINITY;
#pragma unroll
        for (int nt = 0; nt < 8; nt++) {
            mx0 = fmaxf(mx0, fmaxf(s[nt][0], s[nt][1]));
            mx1 = fmaxf(mx1, fmaxf(s[nt][2], s[nt][3]));
        }
        mx0 = fmaxf(mx0, __shfl_xor_sync(0xffffffffu, mx0, 1));
        mx0 = fmaxf(mx0, __shfl_xor_sync(0xffffffffu, mx0, 2));
        mx1 = fmaxf(mx1, __shfl_xor_sync(0xffffffffu, mx1, 1));
        mx1 = fmaxf(mx1, __shfl_xor_sync(0xffffffffu, mx1, 2));
        float mn0 = fmaxf(mrow[0], mx0), mn1 = fmaxf(mrow[1], mx1);
        float al0 = exp2f(mrow[0] - mn0), al1 = exp2f(mrow[1] - mn1);
        mrow[0] = mn0; mrow[1] = mn1;

        // P = 2^(s - mn) directly in packed fp16 (mma A fragments)
        uint32_t p[8][2];
#pragma unroll
        for (int nt = 0; nt < 8; nt++) {
            p[nt][0] = ex2h2(pack_h2(s[nt][0] - mn0, s[nt][1] - mn0));
            p[nt][1] = ex2h2(pack_h2(s[nt][2] - mn1, s[nt][3] - mn1));
        }

        // rescale O and l by alpha
#pragma unroll
        for (int nt = 0; nt < 8; nt++) {
            o[nt][0] *= al0; o[nt][1] *= al0;
            o[nt][2] *= al1; o[nt][3] *= al1;
        }
        lacc[0] *= al0; lacc[2] *= al1;

        // O += P @ V (V B-frags via ldmatrix.trans on [t][d] tile);
        // l += P @ ones (synthetic B fragment, col 0 only)
#pragma unroll
        for (int j = 0; j < 4; j++) {
            uint32_t a[4] = { p[2*j][0], p[2*j][1], p[2*j+1][0], p[2*j+1][1] };
            const int kk = j * 16;
#pragma unroll
            for (int g = 0; g < 4; g++) {
                uint32_t b[4];
                ldsm4t(b, V + swz(kk + v_row, g * 16 + v_col));
                mma16(o[2*g+0], a, b[0], b[1]);
                mma16(o[2*g+1], a, b[2], b[3]);
            }
            mma16(lacc, a, onesb, onesb);
        }

        if (jt + 2 <= jtmax) { KV_LOAD((jt + 2) % 3, (jt + 2) * 64); CP_COMMIT(); }
    }

    {
        // l lives in column 0 of the C fragment -> only lanes with (lane&3)==0.
        // Broadcast from the row-owner lane (lane & 28).
        float l0 = __shfl_sync(0xffffffffu, lacc[0], lane & 28);
        float l1 = __shfl_sync(0xffffffffu, lacc[2], lane & 28);
        float inv0 = 1.f / l0, inv1 = 1.f / l1;
        int row = m0 + wid * 16 + (lane >> 2);
        __half* op = g_attn + ((size_t)bh * SEQ + row) * HDIM;
#pragma unroll
        for (int nt = 0; nt < 8; nt++) {
            int col = nt * 8 + 2 * (lane & 3);
            *(uint32_t*)&op[col] = pack_h2(o[nt][0] * inv0, o[nt][1] * inv0);
            *(uint32_t*)&op[8 * HDIM + col] = pack_h2(o[nt][2] * inv1, o[nt][3] * inv1);
        }
    }
#undef KV_LOAD
}

// ---------------------------------------------------------------------------
// Output projection: out = attn @ wproj^T + bias. Tile 128x128, BK=64,
// 3-stage, one sync per k-tile. grid (64,8), 256 thr.
// ---------------------------------------------------------------------------
__global__ __launch_bounds__(256, 2) void proj_kernel(
    const float* __restrict__ bproj, float* __restrict__ out)
{
    extern __shared__ char smc[];
    const uint32_t sb = smem_u32(smc);
    const uint32_t Ab = sb;
    const uint32_t Bb = sb + 3 * GSTG;

    const int m0 = blockIdx.x * 128, n0 = blockIdx.y * 128;
    const int tid = threadIdx.x;
    const int lane = tid & 31, wid = tid >> 5;
    const int wm = wid & 3, wn = wid >> 2;
    const int lr = lane & 7, ls = lane >> 3;

    float acc[2][8][4];
#pragma unroll
    for (int mt = 0; mt < 2; mt++)
#pragma unroll
        for (int nt = 0; nt < 8; nt++)
#pragma unroll
            for (int c = 0; c < 4; c++) acc[mt][nt][c] = 0.f;

    const int a_row = wm * 32 + (lane & 15);
    const int a_k = (ls >> 1) * 8;
    const int b_row = wn * 64 + lr + ((ls >> 1) << 3);
    const int b_k = (ls & 1) * 8;

#define PROJ_LOAD(st, kt_)                                                    \
    {                                                                         \
        _Pragma("unroll")                                                     \
        for (int it = 0; it < 4; it++) {                                      \
            int idx = tid + it * 256;                                         \
            int r = idx >> 3, ch = (idx & 7) * 8;                             \
            int bt = m0 + r, b_ = bt >> 11, t_ = bt & 2047;                   \
            cp16(Ab + (st) * GSTG + swz(r, ch),                               \
                 &g_attn[(((size_t)(b_ * NHEAD + (kt_))) * SEQ + t_) * HDIM + ch]); \
            cp16(Bb + (st) * GSTG + swz(r, ch),                               \
                 &g_wproj[(size_t)(n0 + r) * EMBD + (kt_) * 64 + ch]);        \
        }                                                                     \
    }

    PROJ_LOAD(0, 0); CP_COMMIT();
    PROJ_LOAD(1, 1); CP_COMMIT();

    for (int kt = 0; kt < 16; kt++) {
        const int cur = kt % 3;
        if (kt >= 14) CP_WAIT0(); else CP_WAIT1();
        __syncthreads();
        const uint32_t A = Ab + cur * GSTG;
        const uint32_t B = Bb + cur * GSTG;
#pragma unroll
        for (int kk = 0; kk < 64; kk += 16) {
            uint32_t a[2][4];
            ldsm4(a[0], A + swz(a_row, kk + a_k));
            ldsm4(a[1], A + swz(a_row + 16, kk + a_k));
#pragma unroll
            for (int g = 0; g < 4; g++) {
                uint32_t b[4];
                ldsm4(b, B + swz(b_row + g * 16, kk + b_k));
                mma16(acc[0][2*g+0], a[0], b[0], b[1]);
                mma16(acc[0][2*g+1], a[0], b[2], b[3]);
                mma16(acc[1][2*g+0], a[1], b[0], b[1]);
                mma16(acc[1][2*g+1], a[1], b[2], b[3]);
            }
        }
        if (kt < 14) { PROJ_LOAD((kt + 2) % 3, kt + 2); CP_COMMIT(); }
    }

#pragma unroll
    for (int mt = 0; mt < 2; mt++) {
        int row = m0 + wm * 32 + mt * 16 + (lane >> 2);
        float* o0 = out + (size_t)row * EMBD;
        float* o1 = out + (size_t)(row + 8) * EMBD;
#pragma unroll
        for (int nt = 0; nt < 8; nt++) {
            int col = n0 + wn * 64 + nt * 8 + 2 * (lane & 3);
            float b0 = bproj[col], b1 = bproj[col + 1];
            *(float2*)&o0[col] = make_float2(acc[mt][nt][0] + b0, acc[mt][nt][1] + b1);
            *(float2*)&o1[col] = make_float2(acc[mt][nt][2] + b0, acc[mt][nt][3] + b1);
        }
    }
#undef PROJ_LOAD
}

// ---------------------------------------------------------------------------
extern "C" void kernel_launch(void* const* d_in, const int* in_sizes, int n_in,
                              void* d_out, int out_size)
{
    const float* x     = (const float*)d_in[0];
    const float* Wq    = (const float*)d_in[1];
    const float* Wk    = (const float*)d_in[2];
    const float* Wv    = (const float*)d_in[3];
    const float* Wproj = (const float*)d_in[4];
    const float* bproj = (const float*)d_in[5];
    float* out = (float*)d_out;

    __half* xt_p;     cudaGetSymbolAddress((void**)&xt_p, g_xt);
    __half* wproj_p;  cudaGetSymbolAddress((void**)&wproj_p, g_wproj);

    cvt_kernel<<<(MTOT * EMBD / 4 + 255) / 256, 256>>>(
        (const float4*)x, (uint2*)xt_p, MTOT * EMBD / 4);
    cvt_kernel<<<(EMBD * EMBD / 4 + 255) / 256, 256>>>(
        (const float4*)Wproj, (uint2*)wproj_p, EMBD * EMBD / 4);
    wt_kernel<<<dim3(EMBD / 32, HDIM / 32, 48), 256>>>(Wq, Wk, Wv);

    const int gemm_smem = 6 * GSTG;                        // 98304
    cudaFuncSetAttribute(qkv_kernel, cudaFuncAttributeMaxDynamicSharedMemorySize, gemm_smem);
    cudaFuncSetAttribute(proj_kernel, cudaFuncAttributeMaxDynamicSharedMemorySize, gemm_smem);

    qkv_kernel<<<dim3(MTOT / 128, NQKV / 128), 256, gemm_smem>>>();

    const int attn_smem = 16384 + 6 * KSTG;                // 65536
    cudaFuncSetAttribute(attn_kernel, cudaFuncAttributeMaxDynamicSharedMemorySize, attn_smem);
    attn_kernel<<<dim3(SEQ / 128, BATCH * NHEAD), 256, attn_smem>>>();

    proj_kernel<<<dim3(MTOT / 128, EMBD / 128), 256, gemm_smem>>>(bproj, out);
}